// round 7
// baseline (speedup 1.0000x reference)
#include <cuda_runtime.h>
#include <cuda_bf16.h>
#include <cstdint>

// Problem constants
#define BATCH 2
#define SLEN 2048
#define DMODEL 1024
#define HEADS 16
#define HD 64
#define MDIM (BATCH * SLEN)   // 4096
#define D3 (3 * DMODEL)       // 3072

// ---------------------------------------------------------------------------
// Scratch (device globals; no allocations allowed)
// ---------------------------------------------------------------------------
__device__ __nv_bfloat16 g_xhi[(size_t)MDIM * DMODEL];
__device__ __nv_bfloat16 g_xlo[(size_t)MDIM * DMODEL];
__device__ __nv_bfloat16 g_w1hi[(size_t)D3 * DMODEL];   // w_qkv^T [3D, D]
__device__ __nv_bfloat16 g_w1lo[(size_t)D3 * DMODEL];
__device__ __nv_bfloat16 g_w2hi[(size_t)DMODEL * DMODEL]; // w_out^T [D, D]
__device__ __nv_bfloat16 g_w2lo[(size_t)DMODEL * DMODEL];
__device__ __nv_bfloat16 g_qkvhi[(size_t)MDIM * D3];    // GEMM1 split output
__device__ __nv_bfloat16 g_qkvlo[(size_t)MDIM * D3];
__device__ __nv_bfloat16 g_ahi[(size_t)MDIM * DMODEL];  // attention split output
__device__ __nv_bfloat16 g_alo[(size_t)MDIM * DMODEL];

// ---------------------------------------------------------------------------
// PTX helpers (sm_80+ only — harness targets base sm_100)
// ---------------------------------------------------------------------------
__device__ __forceinline__ uint32_t smem_u32(const void* p) {
    uint32_t a;
    asm("{ .reg .u64 t; cvta.to.shared.u64 t, %1; cvt.u32.u64 %0, t; }" : "=r"(a) : "l"(p));
    return a;
}
__device__ __forceinline__ void cp16(uint32_t dst, const void* src) {
    asm volatile("cp.async.cg.shared.global [%0], [%1], 16;" :: "r"(dst), "l"(src) : "memory");
}
#define CP_COMMIT() asm volatile("cp.async.commit_group;" ::: "memory")
#define CP_WAIT(n)  asm volatile("cp.async.wait_group %0;" :: "n"(n) : "memory")

#define LDM4(r, addr) \
    asm volatile("ldmatrix.sync.aligned.m8n8.x4.shared.b16 {%0,%1,%2,%3}, [%4];" \
        : "=r"((r)[0]), "=r"((r)[1]), "=r"((r)[2]), "=r"((r)[3]) : "r"(addr))
#define LDM4T(r, addr) \
    asm volatile("ldmatrix.sync.aligned.m8n8.x4.trans.shared.b16 {%0,%1,%2,%3}, [%4];" \
        : "=r"((r)[0]), "=r"((r)[1]), "=r"((r)[2]), "=r"((r)[3]) : "r"(addr))

#define MMA(d, a, b0, b1) \
    asm volatile("mma.sync.aligned.m16n8k16.row.col.f32.bf16.bf16.f32 " \
        "{%0,%1,%2,%3}, {%4,%5,%6,%7}, {%8,%9}, {%0,%1,%2,%3};" \
        : "+f"((d)[0]), "+f"((d)[1]), "+f"((d)[2]), "+f"((d)[3]) \
        : "r"((a)[0]), "r"((a)[1]), "r"((a)[2]), "r"((a)[3]), "r"(b0), "r"(b1))

__device__ __forceinline__ uint32_t packb(float a, float b) {
    __nv_bfloat162 t = __floats2bfloat162_rn(a, b);
    return *reinterpret_cast<uint32_t*>(&t);
}
__device__ __forceinline__ float bhi(float v) {
    return __bfloat162float(__float2bfloat16(v));
}

// Fast exp2: deg-4 poly + exponent stuffing. x <= 0 expected; ~1e-6 rel err.
__device__ __forceinline__ float exp2_fast(float x) {
    x = fmaxf(x, -126.0f);
    int xi = __float2int_rd(x);
    float f = x - (float)xi;
    float p = 0.0135557472f;
    p = fmaf(p, f, 0.0520323690f);
    p = fmaf(p, f, 0.2413797743f);
    p = fmaf(p, f, 0.6930321187f);
    p = fmaf(p, f, 1.0f);
    return __int_as_float((xi + 127) << 23) * p;
}

#define CEXP 0.1803368801111204f   // 0.125 * log2(e)

// ---------------------------------------------------------------------------
// Split fp32 -> (hi, lo) bf16 elementwise
// ---------------------------------------------------------------------------
__global__ __launch_bounds__(256) void split_fp32(
    const float* __restrict__ src, __nv_bfloat16* __restrict__ hi,
    __nv_bfloat16* __restrict__ lo, int n4)
{
    int i = blockIdx.x * blockDim.x + threadIdx.x;
    if (i >= n4) return;
    float4 v = reinterpret_cast<const float4*>(src)[i];
    float f[4] = {v.x, v.y, v.z, v.w};
    uint2 hp, lp;
    hp.x = packb(f[0], f[1]); hp.y = packb(f[2], f[3]);
    lp.x = packb(f[0] - bhi(f[0]), f[1] - bhi(f[1]));
    lp.y = packb(f[2] - bhi(f[2]), f[3] - bhi(f[3]));
    reinterpret_cast<uint2*>(hi)[i] = hp;
    reinterpret_cast<uint2*>(lo)[i] = lp;
}

// ---------------------------------------------------------------------------
// Split + transpose: src [R, C] fp32 -> hiT, loT [C, R] bf16
// ---------------------------------------------------------------------------
__global__ __launch_bounds__(256) void split_transpose(
    const float* __restrict__ src, __nv_bfloat16* __restrict__ hiT,
    __nv_bfloat16* __restrict__ loT, int R, int C)
{
    __shared__ float t[32][33];
    const int c0 = blockIdx.x * 32, r0 = blockIdx.y * 32;
    const int tx = threadIdx.x, ty = threadIdx.y;   // 32 x 8
    #pragma unroll
    for (int j = 0; j < 4; j++)
        t[ty + 8 * j][tx] = src[(size_t)(r0 + ty + 8 * j) * C + c0 + tx];
    __syncthreads();
    #pragma unroll
    for (int j = 0; j < 4; j++) {
        float v = t[tx][ty + 8 * j];
        size_t o = (size_t)(c0 + ty + 8 * j) * R + r0 + tx;
        hiT[o] = __float2bfloat16(v);
        loT[o] = __float2bfloat16(v - bhi(v));
    }
}

// ---------------------------------------------------------------------------
// Warp-MMA GEMM, 3-term bf16 split emulation of fp32.
// CTA tile 128x256, 512 threads (16 warps, 2Mx8N), warp tile 64x32.
// K chunks of 64, 2-stage cp.async. SPLIT_OUT=1: bf16 hi/lo out; else fp32.
// ---------------------------------------------------------------------------
#define A_MAT 18432            // 128 rows * 144 B
#define B_MAT 36864            // 256 rows * 144 B
#define STAGE_BYTES 110592     // 2*A_MAT + 2*B_MAT
#define GSMEM_BYTES 221184     // 2 stages

template<int SPLIT_OUT>
__global__ __launch_bounds__(512, 1) void gemm_mma3(
    const __nv_bfloat16* __restrict__ Ahi, const __nv_bfloat16* __restrict__ Alo,
    const __nv_bfloat16* __restrict__ BThi, const __nv_bfloat16* __restrict__ BTlo,
    float* __restrict__ C, __nv_bfloat16* __restrict__ Chi, __nv_bfloat16* __restrict__ Clo,
    int M, int N, int K)
{
    extern __shared__ char smem[];
    const uint32_t sb = smem_u32(smem);
    const int tid = threadIdx.x;
    const int wid = tid >> 5, lane = tid & 31;
    const int m0 = blockIdx.y << 7, n0 = blockIdx.x << 8;
    const int wm = (wid >> 3) * 64, wn = (wid & 7) * 32;
    const int nc = K >> 6;

    const __nv_bfloat16* gA[2] = { Ahi + (size_t)m0 * K, Alo + (size_t)m0 * K };
    const __nv_bfloat16* gB[2] = { BThi + (size_t)n0 * K, BTlo + (size_t)n0 * K };

    float acc[4][4][4];
    #pragma unroll
    for (int a = 0; a < 4; a++)
        #pragma unroll
        for (int b = 0; b < 4; b++)
            #pragma unroll
            for (int c = 0; c < 4; c++) acc[a][b][c] = 0.f;

    const int rA = lane & 15, hA = lane >> 4;
    const int qB = lane >> 3, r8 = lane & 7;
    const int bRow = (qB >> 1) * 8 + r8, bHalf = qB & 1;

    auto load_stage = [&](int st, int kk) {
        uint32_t base = sb + (uint32_t)st * STAGE_BYTES;
        #pragma unroll
        for (int mat = 0; mat < 2; mat++) {   // A hi/lo: 128 rows x 8 chunks = 1024
            const __nv_bfloat16* g = gA[mat] + kk;
            uint32_t mb = base + (uint32_t)mat * A_MAT;
            #pragma unroll
            for (int j = 0; j < 2; j++) {
                int idx = tid + j * 512;
                int row = idx >> 3, c = idx & 7;
                cp16(mb + (uint32_t)(row * 144 + c * 16), g + (size_t)row * K + c * 8);
            }
        }
        #pragma unroll
        for (int mat = 0; mat < 2; mat++) {   // B hi/lo: 256 rows x 8 chunks = 2048
            const __nv_bfloat16* g = gB[mat] + kk;
            uint32_t mb = base + 2 * A_MAT + (uint32_t)mat * B_MAT;
            #pragma unroll
            for (int j = 0; j < 4; j++) {
                int idx = tid + j * 512;
                int row = idx >> 3, c = idx & 7;
                cp16(mb + (uint32_t)(row * 144 + c * 16), g + (size_t)row * K + c * 8);
            }
        }
        CP_COMMIT();
    };

    auto compute_stage = [&](int st) {
        uint32_t base = sb + (uint32_t)st * STAGE_BYTES;
        const uint32_t sAh = base, sAl = base + A_MAT;
        const uint32_t sBh = base + 2 * A_MAT, sBl = base + 2 * A_MAT + B_MAT;
        #pragma unroll
        for (int ks = 0; ks < 4; ks++) {
            uint32_t aH[4][4], aL[4][4], bH[2][4], bL[2][4];
            #pragma unroll
            for (int mt = 0; mt < 4; mt++) {
                uint32_t off = (uint32_t)((wm + mt * 16 + rA) * 144 + ks * 32 + hA * 16);
                LDM4(aH[mt], sAh + off);
                LDM4(aL[mt], sAl + off);
            }
            #pragma unroll
            for (int bt = 0; bt < 2; bt++) {
                uint32_t off = (uint32_t)((wn + bt * 16 + bRow) * 144 + ks * 32 + bHalf * 16);
                LDM4(bH[bt], sBh + off);
                LDM4(bL[bt], sBl + off);
            }
            #pragma unroll
            for (int mt = 0; mt < 4; mt++)
                #pragma unroll
                for (int nt = 0; nt < 4; nt++) {
                    const int bt = nt >> 1, p = (nt & 1) * 2;
                    MMA(acc[mt][nt], aH[mt], bH[bt][p], bH[bt][p + 1]);
                    MMA(acc[mt][nt], aH[mt], bL[bt][p], bL[bt][p + 1]);
                    MMA(acc[mt][nt], aL[mt], bH[bt][p], bH[bt][p + 1]);
                }
        }
    };

    load_stage(0, 0);
    for (int ic = 0; ic < nc; ic++) {
        if (ic + 1 < nc) { load_stage((ic + 1) & 1, (ic + 1) << 6); CP_WAIT(1); }
        else             { CP_WAIT(0); }
        __syncthreads();
        compute_stage(ic & 1);
        __syncthreads();
    }

    const int rowb = lane >> 2, colb = (lane & 3) * 2;
    #pragma unroll
    for (int mt = 0; mt < 4; mt++)
        #pragma unroll
        for (int nt = 0; nt < 4; nt++) {
            const int r = m0 + wm + mt * 16 + rowb;
            const int cI = n0 + wn + nt * 8 + colb;
            float v0 = acc[mt][nt][0], v1 = acc[mt][nt][1];
            float v2 = acc[mt][nt][2], v3 = acc[mt][nt][3];
            if (SPLIT_OUT) {
                *(uint32_t*)&Chi[(size_t)r * N + cI] = packb(v0, v1);
                *(uint32_t*)&Clo[(size_t)r * N + cI] = packb(v0 - bhi(v0), v1 - bhi(v1));
                *(uint32_t*)&Chi[(size_t)(r + 8) * N + cI] = packb(v2, v3);
                *(uint32_t*)&Clo[(size_t)(r + 8) * N + cI] = packb(v2 - bhi(v2), v3 - bhi(v3));
            } else {
                *(float2*)&C[(size_t)r * N + cI]       = make_float2(v0, v1);
                *(float2*)&C[(size_t)(r + 8) * N + cI] = make_float2(v2, v3);
            }
        }
}

// ---------------------------------------------------------------------------
// Tensor-core causal flash attention, 3-term split for QK and PV.
// Q fragments hoisted to registers (loaded once via ldmatrix at iter 0).
// CTA: 256 threads (8 warps), q-tile 128 (16 rows/warp), k-tile 64.
// ---------------------------------------------------------------------------
#define FQ_BYTES 18432          // 128*144
#define FKV_MAT 9216            // 64*144
#define FSTAGE (4 * FKV_MAT)    // 36864
#define FSMEM (2 * FQ_BYTES + 2 * FSTAGE)   // 110592

__global__ __launch_bounds__(256) void flash_mma(
    const __nv_bfloat16* __restrict__ qhi, const __nv_bfloat16* __restrict__ qlo,
    __nv_bfloat16* __restrict__ outhi, __nv_bfloat16* __restrict__ outlo)
{
    extern __shared__ char smem[];
    const uint32_t sb = smem_u32(smem);
    const uint32_t sQh = sb, sQl = sb + FQ_BYTES;
    const uint32_t sStage = sb + 2 * FQ_BYTES;

    const int tid = threadIdx.x, wid = tid >> 5, lane = tid & 31;
    const int q0 = ((int)gridDim.x - 1 - (int)blockIdx.x) * 128;
    const int h = blockIdx.y, b = blockIdx.z;
    const int qrow0 = q0 + wid * 16;

    const __nv_bfloat16* bhiP = qhi + (size_t)b * SLEN * D3 + h * HD;
    const __nv_bfloat16* bloP = qlo + (size_t)b * SLEN * D3 + h * HD;

    const int rA = lane & 15, hA = lane >> 4;              // A frag (Q, 16 rows)
    const int qB = lane >> 3, r8 = lane & 7;               // B frag (K rows)
    const int bRow = (qB >> 1) * 8 + r8, bHalf = qB & 1;
    const int grp = lane >> 3, l8 = lane & 7;              // V trans frag

    // Stage Q tile (hi+lo)
    {
        #pragma unroll
        for (int j = 0; j < 8; j++) {
            int idx = tid + j * 256;
            int mat = idx >> 10, row = (idx >> 3) & 127, c = idx & 7;
            const __nv_bfloat16* src = (mat ? bloP : bhiP) + (size_t)(q0 + row) * D3 + c * 8;
            cp16((mat ? sQl : sQh) + (uint32_t)(row * 144 + c * 16), src);
        }
    }

    const int nk = q0 / 64 + 2;

    auto load_kv = [&](int st, int k0) {
        uint32_t base = sStage + (uint32_t)st * FSTAGE;
        #pragma unroll
        for (int j = 0; j < 8; j++) {
            int idx = tid + j * 256;
            int mat = idx >> 9, row = (idx >> 3) & 63, c = idx & 7;
            const __nv_bfloat16* base_g = (mat & 1) ? bloP : bhiP;
            int seg = (mat >> 1) ? 2 * DMODEL : DMODEL;
            const __nv_bfloat16* src = base_g + (size_t)(k0 + row) * D3 + seg + c * 8;
            cp16(base + (uint32_t)mat * FKV_MAT + (uint32_t)(row * 144 + c * 16), src);
        }
        CP_COMMIT();
    };

    float oacc[8][4];
    #pragma unroll
    for (int i = 0; i < 8; i++)
        #pragma unroll
        for (int j = 0; j < 4; j++) oacc[i][j] = 0.f;
    float m0 = -1e30f, m1 = -1e30f, l0 = 0.f, l1 = 0.f;

    uint32_t qH[4][4], qL[4][4];   // hoisted Q fragments (per ks)

    load_kv(0, 0);
    CP_COMMIT();

    for (int it = 0; it < nk; it++) {
        const int k0 = it * 64;
        if (it + 1 < nk) { load_kv((it + 1) & 1, (it + 1) * 64); CP_WAIT(1); }
        else             { CP_WAIT(0); }
        __syncthreads();

        if (it == 0) {   // Q data guaranteed resident now; hoist frags once
            #pragma unroll
            for (int ks = 0; ks < 4; ks++) {
                uint32_t aoff = (uint32_t)((wid * 16 + rA) * 144 + ks * 32 + hA * 16);
                LDM4(qH[ks], sQh + aoff);
                LDM4(qL[ks], sQl + aoff);
            }
        }

        if (k0 <= qrow0 + 15) {
            const uint32_t st = sStage + (uint32_t)(it & 1) * FSTAGE;
            const uint32_t sKh = st, sKl = st + FKV_MAT;
            const uint32_t sVh = st + 2 * FKV_MAT, sVl = st + 3 * FKV_MAT;

            // ---- S = Q K^T (3-term split), 16x64 per warp
            float sfrag[8][4];
            #pragma unroll
            for (int i = 0; i < 8; i++)
                #pragma unroll
                for (int j = 0; j < 4; j++) sfrag[i][j] = 0.f;

            #pragma unroll
            for (int ks = 0; ks < 4; ks++) {
                uint32_t kh[4][4], kl[4][4];
                #pragma unroll
                for (int bt = 0; bt < 4; bt++) {
                    uint32_t off = (uint32_t)((bt * 16 + bRow) * 144 + ks * 32 + bHalf * 16);
                    LDM4(kh[bt], sKh + off);
                    LDM4(kl[bt], sKl + off);
                }
                #pragma unroll
                for (int nt = 0; nt < 8; nt++) {
                    const int bt = nt >> 1, p = (nt & 1) * 2;
                    MMA(sfrag[nt], qH[ks], kh[bt][p], kh[bt][p + 1]);
                    MMA(sfrag[nt], qH[ks], kl[bt][p], kl[bt][p + 1]);
                    MMA(sfrag[nt], qL[ks], kh[bt][p], kh[bt][p + 1]);
                }
            }

            // ---- causal mask on diagonal tiles
            const int row0 = qrow0 + (lane >> 2), row1 = row0 + 8;
            if (k0 + 63 > qrow0) {
                #pragma unroll
                for (int nt = 0; nt < 8; nt++) {
                    int col = k0 + nt * 8 + ((lane & 3) << 1);
                    if (col > row0)     sfrag[nt][0] = -1e30f;
                    if (col + 1 > row0) sfrag[nt][1] = -1e30f;
                    if (col > row1)     sfrag[nt][2] = -1e30f;
                    if (col + 1 > row1) sfrag[nt][3] = -1e30f;
                }
            }

            // ---- online softmax
            float mc0 = -1e30f, mc1 = -1e30f;
            #pragma unroll
            for (int nt = 0; nt < 8; nt++) {
                mc0 = fmaxf(mc0, fmaxf(sfrag[nt][0], sfrag[nt][1]));
                mc1 = fmaxf(mc1, fmaxf(sfrag[nt][2], sfrag[nt][3]));
            }
            mc0 = fmaxf(mc0, __shfl_xor_sync(0xffffffffu, mc0, 1));
            mc0 = fmaxf(mc0, __shfl_xor_sync(0xffffffffu, mc0, 2));
            mc1 = fmaxf(mc1, __shfl_xor_sync(0xffffffffu, mc1, 1));
            mc1 = fmaxf(mc1, __shfl_xor_sync(0xffffffffu, mc1, 2));
            const float mn0 = fmaxf(m0, mc0), mn1 = fmaxf(m1, mc1);
            const float corr0 = exp2_fast((m0 - mn0) * CEXP);
            const float corr1 = exp2_fast((m1 - mn1) * CEXP);
            m0 = mn0; m1 = mn1;

            float rs0 = 0.f, rs1 = 0.f;
            #pragma unroll
            for (int nt = 0; nt < 8; nt++) {
                sfrag[nt][0] = exp2_fast((sfrag[nt][0] - mn0) * CEXP);
                sfrag[nt][1] = exp2_fast((sfrag[nt][1] - mn0) * CEXP);
                sfrag[nt][2] = exp2_fast((sfrag[nt][2] - mn1) * CEXP);
                sfrag[nt][3] = exp2_fast((sfrag[nt][3] - mn1) * CEXP);
                rs0 += sfrag[nt][0] + sfrag[nt][1];
                rs1 += sfrag[nt][2] + sfrag[nt][3];
            }
            rs0 += __shfl_xor_sync(0xffffffffu, rs0, 1);
            rs0 += __shfl_xor_sync(0xffffffffu, rs0, 2);
            rs1 += __shfl_xor_sync(0xffffffffu, rs1, 1);
            rs1 += __shfl_xor_sync(0xffffffffu, rs1, 2);
            l0 = l0 * corr0 + rs0;
            l1 = l1 * corr1 + rs1;
            #pragma unroll
            for (int nt = 0; nt < 8; nt++) {
                oacc[nt][0] *= corr0; oacc[nt][1] *= corr0;
                oacc[nt][2] *= corr1; oacc[nt][3] *= corr1;
            }

            // ---- O += P V (3-term split)
            #pragma unroll
            for (int t = 0; t < 4; t++) {
                uint32_t phi[4], plo[4];
                {
                    float p0 = sfrag[2 * t][0], p1 = sfrag[2 * t][1];
                    float p2 = sfrag[2 * t][2], p3 = sfrag[2 * t][3];
                    float p4 = sfrag[2 * t + 1][0], p5 = sfrag[2 * t + 1][1];
                    float p6 = sfrag[2 * t + 1][2], p7 = sfrag[2 * t + 1][3];
                    phi[0] = packb(p0, p1); phi[1] = packb(p2, p3);
                    phi[2] = packb(p4, p5); phi[3] = packb(p6, p7);
                    plo[0] = packb(p0 - bhi(p0), p1 - bhi(p1));
                    plo[1] = packb(p2 - bhi(p2), p3 - bhi(p3));
                    plo[2] = packb(p4 - bhi(p4), p5 - bhi(p5));
                    plo[3] = packb(p6 - bhi(p6), p7 - bhi(p7));
                }
                #pragma unroll
                for (int np = 0; np < 4; np++) {
                    uint32_t vh[4], vl[4];
                    uint32_t off = (uint32_t)((t * 16 + (grp & 1) * 8 + l8) * 144 +
                                              (np * 16 + (grp >> 1) * 8) * 2);
                    LDM4T(vh, sVh + off);
                    LDM4T(vl, sVl + off);
                    const int nt0 = np * 2;
                    MMA(oacc[nt0], phi, vh[0], vh[1]);
                    MMA(oacc[nt0], phi, vl[0], vl[1]);
                    MMA(oacc[nt0], plo, vh[0], vh[1]);
                    MMA(oacc[nt0 + 1], phi, vh[2], vh[3]);
                    MMA(oacc[nt0 + 1], phi, vl[2], vl[3]);
                    MMA(oacc[nt0 + 1], plo, vh[2], vh[3]);
                }
            }
        }
        __syncthreads();
    }

    // ---- finalize
    const float inv0 = 1.f / l0, inv1 = 1.f / l1;
    const int row0 = q0 + wid * 16 + (lane >> 2);
    const int colb = h * HD + (lane & 3) * 2;
    #pragma unroll
    for (int nt = 0; nt < 8; nt++) {
        float v0 = oacc[nt][0] * inv0, v1 = oacc[nt][1] * inv0;
        float v2 = oacc[nt][2] * inv1, v3 = oacc[nt][3] * inv1;
        size_t o0 = (size_t)(b * SLEN + row0) * DMODEL + colb + nt * 8;
        size_t o1 = (size_t)(b * SLEN + row0 + 8) * DMODEL + colb + nt * 8;
        *(uint32_t*)&outhi[o0] = packb(v0, v1);
        *(uint32_t*)&outlo[o0] = packb(v0 - bhi(v0), v1 - bhi(v1));
        *(uint32_t*)&outhi[o1] = packb(v2, v3);
        *(uint32_t*)&outlo[o1] = packb(v2 - bhi(v2), v3 - bhi(v3));
    }
}

// ---------------------------------------------------------------------------
// kernel_launch
// ---------------------------------------------------------------------------
extern "C" void kernel_launch(void* const* d_in, const int* in_sizes, int n_in,
                              void* d_out, int out_size)
{
    const float* x     = (const float*)d_in[0];
    const float* w_qkv = (const float*)d_in[1];
    const float* w_out = (const float*)d_in[2];
    float* out = (float*)d_out;

    __nv_bfloat16 *xhi, *xlo, *w1hi, *w1lo, *w2hi, *w2lo, *qhi, *qlo, *ahi, *alo;
    cudaGetSymbolAddress((void**)&xhi, g_xhi);
    cudaGetSymbolAddress((void**)&xlo, g_xlo);
    cudaGetSymbolAddress((void**)&w1hi, g_w1hi);
    cudaGetSymbolAddress((void**)&w1lo, g_w1lo);
    cudaGetSymbolAddress((void**)&w2hi, g_w2hi);
    cudaGetSymbolAddress((void**)&w2lo, g_w2lo);
    cudaGetSymbolAddress((void**)&qhi, g_qkvhi);
    cudaGetSymbolAddress((void**)&qlo, g_qkvlo);
    cudaGetSymbolAddress((void**)&ahi, g_ahi);
    cudaGetSymbolAddress((void**)&alo, g_alo);

    cudaFuncSetAttribute(gemm_mma3<0>, cudaFuncAttributeMaxDynamicSharedMemorySize, GSMEM_BYTES);
    cudaFuncSetAttribute(gemm_mma3<1>, cudaFuncAttributeMaxDynamicSharedMemorySize, GSMEM_BYTES);
    cudaFuncSetAttribute(flash_mma, cudaFuncAttributeMaxDynamicSharedMemorySize, FSMEM);

    const int M = MDIM;

    split_fp32<<<(M * DMODEL / 4 + 255) / 256, 256>>>(x, xhi, xlo, M * DMODEL / 4);
    split_transpose<<<dim3(D3 / 32, DMODEL / 32), dim3(32, 8)>>>(w_qkv, w1hi, w1lo, DMODEL, D3);
    split_transpose<<<dim3(DMODEL / 32, DMODEL / 32), dim3(32, 8)>>>(w_out, w2hi, w2lo, DMODEL, DMODEL);

    // 1) qkv (split bf16 out) = x @ w_qkv
    gemm_mma3<1><<<dim3(D3 / 256, M / 128), 512, GSMEM_BYTES>>>(
        xhi, xlo, w1hi, w1lo, nullptr, qhi, qlo, M, D3, DMODEL);

    // 2) tensor-core causal flash attention -> split bf16 att
    flash_mma<<<dim3(SLEN / 128, HEADS, BATCH), 256, FSMEM>>>(qhi, qlo, ahi, alo);

    // 3) out = att @ w_out (fp32 out)
    gemm_mma3<0><<<dim3(DMODEL / 256, M / 128), 512, GSMEM_BYTES>>>(
        ahi, alo, w2hi, w2lo, out, nullptr, nullptr, M, DMODEL, DMODEL);
}

// round 8
// speedup vs baseline: 1.3661x; 1.3661x over previous
#include <cuda_runtime.h>
#include <cuda_fp16.h>
#include <cstdint>

// Problem constants
#define BATCH 2
#define SLEN 2048
#define DMODEL 1024
#define HEADS 16
#define HD 64
#define MDIM (BATCH * SLEN)   // 4096
#define D3 (3 * DMODEL)       // 3072

// ---------------------------------------------------------------------------
// Scratch (device globals; no allocations allowed)
// ---------------------------------------------------------------------------
__device__ __half g_xhi[(size_t)MDIM * DMODEL];
__device__ __half g_xlo[(size_t)MDIM * DMODEL];
__device__ __half g_w1h[(size_t)D3 * DMODEL];      // w_qkv^T [3D, D], single fp16
__device__ __half g_w2h[(size_t)DMODEL * DMODEL];  // w_out^T [D, D], single fp16
__device__ __half g_qkvhi[(size_t)MDIM * D3];      // GEMM1 split output
__device__ __half g_qkvlo[(size_t)MDIM * D3];
__device__ __half g_ahi[(size_t)MDIM * DMODEL];    // attention split output
__device__ __half g_alo[(size_t)MDIM * DMODEL];

// ---------------------------------------------------------------------------
// PTX helpers (sm_80+ only — harness targets base sm_100)
// ---------------------------------------------------------------------------
__device__ __forceinline__ uint32_t smem_u32(const void* p) {
    uint32_t a;
    asm("{ .reg .u64 t; cvta.to.shared.u64 t, %1; cvt.u32.u64 %0, t; }" : "=r"(a) : "l"(p));
    return a;
}
__device__ __forceinline__ void cp16(uint32_t dst, const void* src) {
    asm volatile("cp.async.cg.shared.global [%0], [%1], 16;" :: "r"(dst), "l"(src) : "memory");
}
#define CP_COMMIT() asm volatile("cp.async.commit_group;" ::: "memory")
#define CP_WAIT(n)  asm volatile("cp.async.wait_group %0;" :: "n"(n) : "memory")

#define LDM4(r, addr) \
    asm volatile("ldmatrix.sync.aligned.m8n8.x4.shared.b16 {%0,%1,%2,%3}, [%4];" \
        : "=r"((r)[0]), "=r"((r)[1]), "=r"((r)[2]), "=r"((r)[3]) : "r"(addr))
#define LDM4T(r, addr) \
    asm volatile("ldmatrix.sync.aligned.m8n8.x4.trans.shared.b16 {%0,%1,%2,%3}, [%4];" \
        : "=r"((r)[0]), "=r"((r)[1]), "=r"((r)[2]), "=r"((r)[3]) : "r"(addr))

#define MMA(d, a, b0, b1) \
    asm volatile("mma.sync.aligned.m16n8k16.row.col.f32.f16.f16.f32 " \
        "{%0,%1,%2,%3}, {%4,%5,%6,%7}, {%8,%9}, {%0,%1,%2,%3};" \
        : "+f"((d)[0]), "+f"((d)[1]), "+f"((d)[2]), "+f"((d)[3]) \
        : "r"((a)[0]), "r"((a)[1]), "r"((a)[2]), "r"((a)[3]), "r"(b0), "r"(b1))

__device__ __forceinline__ uint32_t packh(float a, float b) {
    __half2 t = __floats2half2_rn(a, b);
    return *reinterpret_cast<uint32_t*>(&t);
}
__device__ __forceinline__ float hhi(float v) {
    return __half2float(__float2half_rn(v));
}

// Fast exp2: deg-4 poly + exponent stuffing. x <= 0 expected; ~1e-6 rel err.
__device__ __forceinline__ float exp2_fast(float x) {
    x = fmaxf(x, -126.0f);
    int xi = __float2int_rd(x);
    float f = x - (float)xi;
    float p = 0.0135557472f;
    p = fmaf(p, f, 0.0520323690f);
    p = fmaf(p, f, 0.2413797743f);
    p = fmaf(p, f, 0.6930321187f);
    p = fmaf(p, f, 1.0f);
    return __int_as_float((xi + 127) << 23) * p;
}

#define CEXP 0.1803368801111204f   // 0.125 * log2(e)

// ---------------------------------------------------------------------------
// Split fp32 -> (hi, lo) fp16 elementwise
// ---------------------------------------------------------------------------
__global__ __launch_bounds__(256) void split_fp32(
    const float* __restrict__ src, __half* __restrict__ hi,
    __half* __restrict__ lo, int n4)
{
    int i = blockIdx.x * blockDim.x + threadIdx.x;
    if (i >= n4) return;
    float4 v = reinterpret_cast<const float4*>(src)[i];
    float f[4] = {v.x, v.y, v.z, v.w};
    uint2 hp, lp;
    hp.x = packh(f[0], f[1]); hp.y = packh(f[2], f[3]);
    lp.x = packh(f[0] - hhi(f[0]), f[1] - hhi(f[1]));
    lp.y = packh(f[2] - hhi(f[2]), f[3] - hhi(f[3]));
    reinterpret_cast<uint2*>(hi)[i] = hp;
    reinterpret_cast<uint2*>(lo)[i] = lp;
}

// ---------------------------------------------------------------------------
// Transpose to single fp16: src [R, C] fp32 -> hT [C, R] fp16
// ---------------------------------------------------------------------------
__global__ __launch_bounds__(256) void transpose_h(
    const float* __restrict__ src, __half* __restrict__ hT, int R, int C)
{
    __shared__ float t[32][33];
    const int c0 = blockIdx.x * 32, r0 = blockIdx.y * 32;
    const int tx = threadIdx.x, ty = threadIdx.y;   // 32 x 8
    #pragma unroll
    for (int j = 0; j < 4; j++)
        t[ty + 8 * j][tx] = src[(size_t)(r0 + ty + 8 * j) * C + c0 + tx];
    __syncthreads();
    #pragma unroll
    for (int j = 0; j < 4; j++)
        hT[(size_t)(c0 + ty + 8 * j) * R + r0 + tx] = __float2half_rn(t[tx][ty + 8 * j]);
}

// ---------------------------------------------------------------------------
// Warp-MMA GEMM, fp16 2-term emulation (A = Ah+Al split fp16, B single fp16).
// CTA tile 128x256, 512 threads (16 warps, 2Mx8N), warp tile 64x32.
// K chunks of 64, 2-stage cp.async. SPLIT_OUT=1: fp16 hi/lo out; else fp32.
// ---------------------------------------------------------------------------
#define A_MAT 18432            // 128 rows * 144 B
#define B_MAT 36864            // 256 rows * 144 B
#define STAGE_BYTES 73728      // 2*A_MAT + B_MAT
#define GSMEM_BYTES 147456     // 2 stages

template<int SPLIT_OUT>
__global__ __launch_bounds__(512, 1) void gemm_mma2(
    const __half* __restrict__ Ahi, const __half* __restrict__ Alo,
    const __half* __restrict__ BT,
    float* __restrict__ C, __half* __restrict__ Chi, __half* __restrict__ Clo,
    int M, int N, int K)
{
    extern __shared__ char smem[];
    const uint32_t sb = smem_u32(smem);
    const int tid = threadIdx.x;
    const int wid = tid >> 5, lane = tid & 31;
    const int m0 = blockIdx.y << 7, n0 = blockIdx.x << 8;
    const int wm = (wid >> 3) * 64, wn = (wid & 7) * 32;
    const int nc = K >> 6;

    const __half* gA[2] = { Ahi + (size_t)m0 * K, Alo + (size_t)m0 * K };
    const __half* gB = BT + (size_t)n0 * K;

    float acc[4][4][4];
    #pragma unroll
    for (int a = 0; a < 4; a++)
        #pragma unroll
        for (int b = 0; b < 4; b++)
            #pragma unroll
            for (int c = 0; c < 4; c++) acc[a][b][c] = 0.f;

    const int rA = lane & 15, hA = lane >> 4;
    const int qB = lane >> 3, r8 = lane & 7;
    const int bRow = (qB >> 1) * 8 + r8, bHalf = qB & 1;

    auto load_stage = [&](int st, int kk) {
        uint32_t base = sb + (uint32_t)st * STAGE_BYTES;
        #pragma unroll
        for (int mat = 0; mat < 2; mat++) {   // A hi/lo: 1024 chunks each
            const __half* g = gA[mat] + kk;
            uint32_t mb = base + (uint32_t)mat * A_MAT;
            #pragma unroll
            for (int j = 0; j < 2; j++) {
                int idx = tid + j * 512;
                int row = idx >> 3, c = idx & 7;
                cp16(mb + (uint32_t)(row * 144 + c * 16), g + (size_t)row * K + c * 8);
            }
        }
        {   // B single: 2048 chunks
            const __half* g = gB + kk;
            uint32_t mb = base + 2 * A_MAT;
            #pragma unroll
            for (int j = 0; j < 4; j++) {
                int idx = tid + j * 512;
                int row = idx >> 3, c = idx & 7;
                cp16(mb + (uint32_t)(row * 144 + c * 16), g + (size_t)row * K + c * 8);
            }
        }
        CP_COMMIT();
    };

    auto compute_stage = [&](int st) {
        uint32_t base = sb + (uint32_t)st * STAGE_BYTES;
        const uint32_t sAh = base, sAl = base + A_MAT;
        const uint32_t sB = base + 2 * A_MAT;
        #pragma unroll
        for (int ks = 0; ks < 4; ks++) {
            uint32_t aH[4][4], aL[4][4], bH[2][4];
            #pragma unroll
            for (int mt = 0; mt < 4; mt++) {
                uint32_t off = (uint32_t)((wm + mt * 16 + rA) * 144 + ks * 32 + hA * 16);
                LDM4(aH[mt], sAh + off);
                LDM4(aL[mt], sAl + off);
            }
            #pragma unroll
            for (int bt = 0; bt < 2; bt++) {
                uint32_t off = (uint32_t)((wn + bt * 16 + bRow) * 144 + ks * 32 + bHalf * 16);
                LDM4(bH[bt], sB + off);
            }
            #pragma unroll
            for (int mt = 0; mt < 4; mt++)
                #pragma unroll
                for (int nt = 0; nt < 4; nt++) {
                    const int bt = nt >> 1, p = (nt & 1) * 2;
                    MMA(acc[mt][nt], aH[mt], bH[bt][p], bH[bt][p + 1]);
                    MMA(acc[mt][nt], aL[mt], bH[bt][p], bH[bt][p + 1]);
                }
        }
    };

    load_stage(0, 0);
    for (int ic = 0; ic < nc; ic++) {
        if (ic + 1 < nc) { load_stage((ic + 1) & 1, (ic + 1) << 6); CP_WAIT(1); }
        else             { CP_WAIT(0); }
        __syncthreads();
        compute_stage(ic & 1);
        __syncthreads();
    }

    const int rowb = lane >> 2, colb = (lane & 3) * 2;
    #pragma unroll
    for (int mt = 0; mt < 4; mt++)
        #pragma unroll
        for (int nt = 0; nt < 4; nt++) {
            const int r = m0 + wm + mt * 16 + rowb;
            const int cI = n0 + wn + nt * 8 + colb;
            float v0 = acc[mt][nt][0], v1 = acc[mt][nt][1];
            float v2 = acc[mt][nt][2], v3 = acc[mt][nt][3];
            if (SPLIT_OUT) {
                *(uint32_t*)&Chi[(size_t)r * N + cI] = packh(v0, v1);
                *(uint32_t*)&Clo[(size_t)r * N + cI] = packh(v0 - hhi(v0), v1 - hhi(v1));
                *(uint32_t*)&Chi[(size_t)(r + 8) * N + cI] = packh(v2, v3);
                *(uint32_t*)&Clo[(size_t)(r + 8) * N + cI] = packh(v2 - hhi(v2), v3 - hhi(v3));
            } else {
                *(float2*)&C[(size_t)r * N + cI]       = make_float2(v0, v1);
                *(float2*)&C[(size_t)(r + 8) * N + cI] = make_float2(v2, v3);
            }
        }
}

// ---------------------------------------------------------------------------
// Tensor-core causal flash attention, fp16 2-term (Q,P split; K,V single).
// Q fragments hoisted to registers. CTA: 256 threads (8 warps), q-tile 128,
// k-tile 64, 2-stage cp.async KV pipeline.
// ---------------------------------------------------------------------------
#define FQ_BYTES 18432          // 128*144
#define FKV_MAT 9216            // 64*144
#define FSTAGE (2 * FKV_MAT)    // 18432 (Kh + Vh)
#define FSMEM (2 * FQ_BYTES + 2 * FSTAGE)   // 73728

__global__ __launch_bounds__(256) void flash_mma(
    const __half* __restrict__ qhi, const __half* __restrict__ qlo,
    __half* __restrict__ outhi, __half* __restrict__ outlo)
{
    extern __shared__ char smem[];
    const uint32_t sb = smem_u32(smem);
    const uint32_t sQh = sb, sQl = sb + FQ_BYTES;
    const uint32_t sStage = sb + 2 * FQ_BYTES;

    const int tid = threadIdx.x, wid = tid >> 5, lane = tid & 31;
    const int q0 = ((int)gridDim.x - 1 - (int)blockIdx.x) * 128;
    const int h = blockIdx.y, b = blockIdx.z;
    const int qrow0 = q0 + wid * 16;

    const __half* bhiP = qhi + (size_t)b * SLEN * D3 + h * HD;
    const __half* bloP = qlo + (size_t)b * SLEN * D3 + h * HD;

    const int rA = lane & 15, hA = lane >> 4;              // A frag (Q rows)
    const int qB = lane >> 3, r8 = lane & 7;               // B frag (K rows)
    const int bRow = (qB >> 1) * 8 + r8, bHalf = qB & 1;
    const int grp = lane >> 3, l8 = lane & 7;              // V trans frag

    // Stage Q tile (hi+lo): 2048 chunks
    {
        #pragma unroll
        for (int j = 0; j < 8; j++) {
            int idx = tid + j * 256;
            int mat = idx >> 10, row = (idx >> 3) & 127, c = idx & 7;
            const __half* src = (mat ? bloP : bhiP) + (size_t)(q0 + row) * D3 + c * 8;
            cp16((mat ? sQl : sQh) + (uint32_t)(row * 144 + c * 16), src);
        }
    }

    const int nk = q0 / 64 + 2;

    auto load_kv = [&](int st, int k0) {
        uint32_t base = sStage + (uint32_t)st * FSTAGE;
        #pragma unroll
        for (int j = 0; j < 4; j++) {   // Kh + Vh: 1024 chunks
            int idx = tid + j * 256;
            int mat = idx >> 9, row = (idx >> 3) & 63, c = idx & 7;
            int seg = mat ? 2 * DMODEL : DMODEL;   // 0=K, 1=V
            const __half* src = bhiP + (size_t)(k0 + row) * D3 + seg + c * 8;
            cp16(base + (uint32_t)mat * FKV_MAT + (uint32_t)(row * 144 + c * 16), src);
        }
        CP_COMMIT();
    };

    float oacc[8][4];
    #pragma unroll
    for (int i = 0; i < 8; i++)
        #pragma unroll
        for (int j = 0; j < 4; j++) oacc[i][j] = 0.f;
    float m0 = -1e30f, m1 = -1e30f, l0 = 0.f, l1 = 0.f;

    uint32_t qH[4][4], qL[4][4];   // hoisted Q fragments (per ks)

    load_kv(0, 0);
    CP_COMMIT();

    for (int it = 0; it < nk; it++) {
        const int k0 = it * 64;
        if (it + 1 < nk) { load_kv((it + 1) & 1, (it + 1) * 64); CP_WAIT(1); }
        else             { CP_WAIT(0); }
        __syncthreads();

        if (it == 0) {   // Q resident now; hoist frags once
            #pragma unroll
            for (int ks = 0; ks < 4; ks++) {
                uint32_t aoff = (uint32_t)((wid * 16 + rA) * 144 + ks * 32 + hA * 16);
                LDM4(qH[ks], sQh + aoff);
                LDM4(qL[ks], sQl + aoff);
            }
        }

        if (k0 <= qrow0 + 15) {
            const uint32_t st = sStage + (uint32_t)(it & 1) * FSTAGE;
            const uint32_t sKh = st, sVh = st + FKV_MAT;

            // ---- S = Q K^T (2-term), 16x64 per warp
            float sfrag[8][4];
            #pragma unroll
            for (int i = 0; i < 8; i++)
                #pragma unroll
                for (int j = 0; j < 4; j++) sfrag[i][j] = 0.f;

            #pragma unroll
            for (int ks = 0; ks < 4; ks++) {
                uint32_t kh[4][4];
                #pragma unroll
                for (int bt = 0; bt < 4; bt++) {
                    uint32_t off = (uint32_t)((bt * 16 + bRow) * 144 + ks * 32 + bHalf * 16);
                    LDM4(kh[bt], sKh + off);
                }
                #pragma unroll
                for (int nt = 0; nt < 8; nt++) {
                    const int bt = nt >> 1, p = (nt & 1) * 2;
                    MMA(sfrag[nt], qH[ks], kh[bt][p], kh[bt][p + 1]);
                    MMA(sfrag[nt], qL[ks], kh[bt][p], kh[bt][p + 1]);
                }
            }

            // ---- causal mask on diagonal tiles
            const int row0 = qrow0 + (lane >> 2), row1 = row0 + 8;
            if (k0 + 63 > qrow0) {
                #pragma unroll
                for (int nt = 0; nt < 8; nt++) {
                    int col = k0 + nt * 8 + ((lane & 3) << 1);
                    if (col > row0)     sfrag[nt][0] = -1e30f;
                    if (col + 1 > row0) sfrag[nt][1] = -1e30f;
                    if (col > row1)     sfrag[nt][2] = -1e30f;
                    if (col + 1 > row1) sfrag[nt][3] = -1e30f;
                }
            }

            // ---- online softmax
            float mc0 = -1e30f, mc1 = -1e30f;
            #pragma unroll
            for (int nt = 0; nt < 8; nt++) {
                mc0 = fmaxf(mc0, fmaxf(sfrag[nt][0], sfrag[nt][1]));
                mc1 = fmaxf(mc1, fmaxf(sfrag[nt][2], sfrag[nt][3]));
            }
            mc0 = fmaxf(mc0, __shfl_xor_sync(0xffffffffu, mc0, 1));
            mc0 = fmaxf(mc0, __shfl_xor_sync(0xffffffffu, mc0, 2));
            mc1 = fmaxf(mc1, __shfl_xor_sync(0xffffffffu, mc1, 1));
            mc1 = fmaxf(mc1, __shfl_xor_sync(0xffffffffu, mc1, 2));
            const float mn0 = fmaxf(m0, mc0), mn1 = fmaxf(m1, mc1);
            const float corr0 = exp2_fast((m0 - mn0) * CEXP);
            const float corr1 = exp2_fast((m1 - mn1) * CEXP);
            m0 = mn0; m1 = mn1;

            float rs0 = 0.f, rs1 = 0.f;
            #pragma unroll
            for (int nt = 0; nt < 8; nt++) {
                sfrag[nt][0] = exp2_fast((sfrag[nt][0] - mn0) * CEXP);
                sfrag[nt][1] = exp2_fast((sfrag[nt][1] - mn0) * CEXP);
                sfrag[nt][2] = exp2_fast((sfrag[nt][2] - mn1) * CEXP);
                sfrag[nt][3] = exp2_fast((sfrag[nt][3] - mn1) * CEXP);
                rs0 += sfrag[nt][0] + sfrag[nt][1];
                rs1 += sfrag[nt][2] + sfrag[nt][3];
            }
            rs0 += __shfl_xor_sync(0xffffffffu, rs0, 1);
            rs0 += __shfl_xor_sync(0xffffffffu, rs0, 2);
            rs1 += __shfl_xor_sync(0xffffffffu, rs1, 1);
            rs1 += __shfl_xor_sync(0xffffffffu, rs1, 2);
            l0 = l0 * corr0 + rs0;
            l1 = l1 * corr1 + rs1;
            #pragma unroll
            for (int nt = 0; nt < 8; nt++) {
                oacc[nt][0] *= corr0; oacc[nt][1] *= corr0;
                oacc[nt][2] *= corr1; oacc[nt][3] *= corr1;
            }

            // ---- O += P V (P split, V single)
            #pragma unroll
            for (int t = 0; t < 4; t++) {
                uint32_t phi[4], plo[4];
                {
                    float p0 = sfrag[2 * t][0], p1 = sfrag[2 * t][1];
                    float p2 = sfrag[2 * t][2], p3 = sfrag[2 * t][3];
                    float p4 = sfrag[2 * t + 1][0], p5 = sfrag[2 * t + 1][1];
                    float p6 = sfrag[2 * t + 1][2], p7 = sfrag[2 * t + 1][3];
                    phi[0] = packh(p0, p1); phi[1] = packh(p2, p3);
                    phi[2] = packh(p4, p5); phi[3] = packh(p6, p7);
                    plo[0] = packh(p0 - hhi(p0), p1 - hhi(p1));
                    plo[1] = packh(p2 - hhi(p2), p3 - hhi(p3));
                    plo[2] = packh(p4 - hhi(p4), p5 - hhi(p5));
                    plo[3] = packh(p6 - hhi(p6), p7 - hhi(p7));
                }
                #pragma unroll
                for (int np = 0; np < 4; np++) {
                    uint32_t vh[4];
                    uint32_t off = (uint32_t)((t * 16 + (grp & 1) * 8 + l8) * 144 +
                                              (np * 16 + (grp >> 1) * 8) * 2);
                    LDM4T(vh, sVh + off);
                    const int nt0 = np * 2;
                    MMA(oacc[nt0], phi, vh[0], vh[1]);
                    MMA(oacc[nt0], plo, vh[0], vh[1]);
                    MMA(oacc[nt0 + 1], phi, vh[2], vh[3]);
                    MMA(oacc[nt0 + 1], plo, vh[2], vh[3]);
                }
            }
        }
        __syncthreads();
    }

    // ---- finalize
    const float inv0 = 1.f / l0, inv1 = 1.f / l1;
    const int row0 = q0 + wid * 16 + (lane >> 2);
    const int colb = h * HD + (lane & 3) * 2;
    #pragma unroll
    for (int nt = 0; nt < 8; nt++) {
        float v0 = oacc[nt][0] * inv0, v1 = oacc[nt][1] * inv0;
        float v2 = oacc[nt][2] * inv1, v3 = oacc[nt][3] * inv1;
        size_t o0 = (size_t)(b * SLEN + row0) * DMODEL + colb + nt * 8;
        size_t o1 = (size_t)(b * SLEN + row0 + 8) * DMODEL + colb + nt * 8;
        *(uint32_t*)&outhi[o0] = packh(v0, v1);
        *(uint32_t*)&outlo[o0] = packh(v0 - hhi(v0), v1 - hhi(v1));
        *(uint32_t*)&outhi[o1] = packh(v2, v3);
        *(uint32_t*)&outlo[o1] = packh(v2 - hhi(v2), v3 - hhi(v3));
    }
}

// ---------------------------------------------------------------------------
// kernel_launch
// ---------------------------------------------------------------------------
extern "C" void kernel_launch(void* const* d_in, const int* in_sizes, int n_in,
                              void* d_out, int out_size)
{
    const float* x     = (const float*)d_in[0];
    const float* w_qkv = (const float*)d_in[1];
    const float* w_out = (const float*)d_in[2];
    float* out = (float*)d_out;

    __half *xhi, *xlo, *w1h, *w2h, *qhi, *qlo, *ahi, *alo;
    cudaGetSymbolAddress((void**)&xhi, g_xhi);
    cudaGetSymbolAddress((void**)&xlo, g_xlo);
    cudaGetSymbolAddress((void**)&w1h, g_w1h);
    cudaGetSymbolAddress((void**)&w2h, g_w2h);
    cudaGetSymbolAddress((void**)&qhi, g_qkvhi);
    cudaGetSymbolAddress((void**)&qlo, g_qkvlo);
    cudaGetSymbolAddress((void**)&ahi, g_ahi);
    cudaGetSymbolAddress((void**)&alo, g_alo);

    cudaFuncSetAttribute(gemm_mma2<0>, cudaFuncAttributeMaxDynamicSharedMemorySize, GSMEM_BYTES);
    cudaFuncSetAttribute(gemm_mma2<1>, cudaFuncAttributeMaxDynamicSharedMemorySize, GSMEM_BYTES);
    cudaFuncSetAttribute(flash_mma, cudaFuncAttributeMaxDynamicSharedMemorySize, FSMEM);

    const int M = MDIM;

    split_fp32<<<(M * DMODEL / 4 + 255) / 256, 256>>>(x, xhi, xlo, M * DMODEL / 4);
    transpose_h<<<dim3(D3 / 32, DMODEL / 32), dim3(32, 8)>>>(w_qkv, w1h, DMODEL, D3);
    transpose_h<<<dim3(DMODEL / 32, DMODEL / 32), dim3(32, 8)>>>(w_out, w2h, DMODEL, DMODEL);

    // 1) qkv (split fp16 out) = x @ w_qkv
    gemm_mma2<1><<<dim3(D3 / 256, M / 128), 512, GSMEM_BYTES>>>(
        xhi, xlo, w1h, nullptr, qhi, qlo, M, D3, DMODEL);

    // 2) tensor-core causal flash attention -> split fp16 att
    flash_mma<<<dim3(SLEN / 128, HEADS, BATCH), 256, FSMEM>>>(qhi, qlo, ahi, alo);

    // 3) out = att @ w_out (fp32 out)
    gemm_mma2<0><<<dim3(DMODEL / 256, M / 128), 512, GSMEM_BYTES>>>(
        ahi, alo, w2h, out, nullptr, nullptr, M, DMODEL, DMODEL);
}

// round 9
// speedup vs baseline: 1.4101x; 1.0323x over previous
#include <cuda_runtime.h>
#include <cuda_fp16.h>
#include <cstdint>

// Problem constants
#define BATCH 2
#define SLEN 2048
#define DMODEL 1024
#define HEADS 16
#define HD 64
#define MDIM (BATCH * SLEN)   // 4096
#define D3 (3 * DMODEL)       // 3072

// ---------------------------------------------------------------------------
// Scratch (device globals; no allocations allowed)
// ---------------------------------------------------------------------------
__device__ __half g_xhi[(size_t)MDIM * DMODEL];
__device__ __half g_xlo[(size_t)MDIM * DMODEL];
__device__ __half g_w1h[(size_t)D3 * DMODEL];      // w_qkv^T [3D, D], single fp16
__device__ __half g_w2h[(size_t)DMODEL * DMODEL];  // w_out^T [D, D], single fp16
__device__ __half g_qkvhi[(size_t)MDIM * D3];      // GEMM1 split output
__device__ __half g_qkvlo[(size_t)MDIM * D3];
__device__ __half g_ahi[(size_t)MDIM * DMODEL];    // attention split output
__device__ __half g_alo[(size_t)MDIM * DMODEL];

// ---------------------------------------------------------------------------
// PTX helpers (sm_80+ only — harness targets base sm_100)
// ---------------------------------------------------------------------------
__device__ __forceinline__ uint32_t smem_u32(const void* p) {
    uint32_t a;
    asm("{ .reg .u64 t; cvta.to.shared.u64 t, %1; cvt.u32.u64 %0, t; }" : "=r"(a) : "l"(p));
    return a;
}
__device__ __forceinline__ void cp16(uint32_t dst, const void* src) {
    asm volatile("cp.async.cg.shared.global [%0], [%1], 16;" :: "r"(dst), "l"(src) : "memory");
}
#define CP_COMMIT() asm volatile("cp.async.commit_group;" ::: "memory")
#define CP_WAIT(n)  asm volatile("cp.async.wait_group %0;" :: "n"(n) : "memory")

#define LDM4(r, addr) \
    asm volatile("ldmatrix.sync.aligned.m8n8.x4.shared.b16 {%0,%1,%2,%3}, [%4];" \
        : "=r"((r)[0]), "=r"((r)[1]), "=r"((r)[2]), "=r"((r)[3]) : "r"(addr))
#define LDM4T(r, addr) \
    asm volatile("ldmatrix.sync.aligned.m8n8.x4.trans.shared.b16 {%0,%1,%2,%3}, [%4];" \
        : "=r"((r)[0]), "=r"((r)[1]), "=r"((r)[2]), "=r"((r)[3]) : "r"(addr))

#define MMA(d, a, b0, b1) \
    asm volatile("mma.sync.aligned.m16n8k16.row.col.f32.f16.f16.f32 " \
        "{%0,%1,%2,%3}, {%4,%5,%6,%7}, {%8,%9}, {%0,%1,%2,%3};" \
        : "+f"((d)[0]), "+f"((d)[1]), "+f"((d)[2]), "+f"((d)[3]) \
        : "r"((a)[0]), "r"((a)[1]), "r"((a)[2]), "r"((a)[3]), "r"(b0), "r"(b1))

__device__ __forceinline__ uint32_t packh(float a, float b) {
    __half2 t = __floats2half2_rn(a, b);
    return *reinterpret_cast<uint32_t*>(&t);
}
__device__ __forceinline__ float hhi(float v) {
    return __half2float(__float2half_rn(v));
}

// Fast exp2: deg-4 poly + exponent stuffing. x <= 0 expected; ~1e-6 rel err.
__device__ __forceinline__ float exp2_fast(float x) {
    x = fmaxf(x, -126.0f);
    int xi = __float2int_rd(x);
    float f = x - (float)xi;
    float p = 0.0135557472f;
    p = fmaf(p, f, 0.0520323690f);
    p = fmaf(p, f, 0.2413797743f);
    p = fmaf(p, f, 0.6930321187f);
    p = fmaf(p, f, 1.0f);
    return __int_as_float((xi + 127) << 23) * p;
}

#define CEXP 0.1803368801111204f   // 0.125 * log2(e)

// ---------------------------------------------------------------------------
// Split fp32 -> (hi, lo) fp16 elementwise
// ---------------------------------------------------------------------------
__global__ __launch_bounds__(256) void split_fp32(
    const float* __restrict__ src, __half* __restrict__ hi,
    __half* __restrict__ lo, int n4)
{
    int i = blockIdx.x * blockDim.x + threadIdx.x;
    if (i >= n4) return;
    float4 v = reinterpret_cast<const float4*>(src)[i];
    float f[4] = {v.x, v.y, v.z, v.w};
    uint2 hp, lp;
    hp.x = packh(f[0], f[1]); hp.y = packh(f[2], f[3]);
    lp.x = packh(f[0] - hhi(f[0]), f[1] - hhi(f[1]));
    lp.y = packh(f[2] - hhi(f[2]), f[3] - hhi(f[3]));
    reinterpret_cast<uint2*>(hi)[i] = hp;
    reinterpret_cast<uint2*>(lo)[i] = lp;
}

// ---------------------------------------------------------------------------
// Transpose to single fp16: src [R, C] fp32 -> hT [C, R] fp16
// ---------------------------------------------------------------------------
__global__ __launch_bounds__(256) void transpose_h(
    const float* __restrict__ src, __half* __restrict__ hT, int R, int C)
{
    __shared__ float t[32][33];
    const int c0 = blockIdx.x * 32, r0 = blockIdx.y * 32;
    const int tx = threadIdx.x, ty = threadIdx.y;   // 32 x 8
    #pragma unroll
    for (int j = 0; j < 4; j++)
        t[ty + 8 * j][tx] = src[(size_t)(r0 + ty + 8 * j) * C + c0 + tx];
    __syncthreads();
    #pragma unroll
    for (int j = 0; j < 4; j++)
        hT[(size_t)(c0 + ty + 8 * j) * R + r0 + tx] = __float2half_rn(t[tx][ty + 8 * j]);
}

// ---------------------------------------------------------------------------
// Warp-MMA GEMM, fp16 2-term emulation (A = Ah+Al split fp16, B single fp16).
// CTA tile 128x128, 256 threads (8 warps, 2Mx4N), warp tile 64x32.
// 2-stage cp.async, 110.6 KB smem -> 2 CTAs/SM for sync-shadow overlap.
// SPLIT_OUT=1: fp16 hi/lo out; else fp32.
// ---------------------------------------------------------------------------
#define A_MAT 18432            // 128 rows * 144 B
#define STAGE_BYTES 55296      // 2*A_MAT (A hi/lo) + A_MAT (B)
#define GSMEM_BYTES 110592     // 2 stages

template<int SPLIT_OUT>
__global__ __launch_bounds__(256, 2) void gemm_mma2(
    const __half* __restrict__ Ahi, const __half* __restrict__ Alo,
    const __half* __restrict__ BT,
    float* __restrict__ C, __half* __restrict__ Chi, __half* __restrict__ Clo,
    int M, int N, int K)
{
    extern __shared__ char smem[];
    const uint32_t sb = smem_u32(smem);
    const int tid = threadIdx.x;
    const int wid = tid >> 5, lane = tid & 31;
    const int m0 = blockIdx.y << 7, n0 = blockIdx.x << 7;
    const int wm = (wid >> 2) * 64, wn = (wid & 3) * 32;
    const int nc = K >> 6;

    const __half* gA[2] = { Ahi + (size_t)m0 * K, Alo + (size_t)m0 * K };
    const __half* gB = BT + (size_t)n0 * K;

    float acc[4][4][4];
    #pragma unroll
    for (int a = 0; a < 4; a++)
        #pragma unroll
        for (int b = 0; b < 4; b++)
            #pragma unroll
            for (int c = 0; c < 4; c++) acc[a][b][c] = 0.f;

    const int rA = lane & 15, hA = lane >> 4;
    const int qB = lane >> 3, r8 = lane & 7;
    const int bRow = (qB >> 1) * 8 + r8, bHalf = qB & 1;

    auto load_stage = [&](int st, int kk) {
        uint32_t base = sb + (uint32_t)st * STAGE_BYTES;
        #pragma unroll
        for (int mat = 0; mat < 2; mat++) {   // A hi/lo: 1024 chunks each
            const __half* g = gA[mat] + kk;
            uint32_t mb = base + (uint32_t)mat * A_MAT;
            #pragma unroll
            for (int j = 0; j < 4; j++) {
                int idx = tid + j * 256;
                int row = idx >> 3, c = idx & 7;
                cp16(mb + (uint32_t)(row * 144 + c * 16), g + (size_t)row * K + c * 8);
            }
        }
        {   // B single: 1024 chunks
            const __half* g = gB + kk;
            uint32_t mb = base + 2 * A_MAT;
            #pragma unroll
            for (int j = 0; j < 4; j++) {
                int idx = tid + j * 256;
                int row = idx >> 3, c = idx & 7;
                cp16(mb + (uint32_t)(row * 144 + c * 16), g + (size_t)row * K + c * 8);
            }
        }
        CP_COMMIT();
    };

    auto compute_stage = [&](int st) {
        uint32_t base = sb + (uint32_t)st * STAGE_BYTES;
        const uint32_t sAh = base, sAl = base + A_MAT;
        const uint32_t sB = base + 2 * A_MAT;
        #pragma unroll
        for (int ks = 0; ks < 4; ks++) {
            uint32_t aH[4][4], aL[4][4], bH[2][4];
            #pragma unroll
            for (int mt = 0; mt < 4; mt++) {
                uint32_t off = (uint32_t)((wm + mt * 16 + rA) * 144 + ks * 32 + hA * 16);
                LDM4(aH[mt], sAh + off);
                LDM4(aL[mt], sAl + off);
            }
            #pragma unroll
            for (int bt = 0; bt < 2; bt++) {
                uint32_t off = (uint32_t)((wn + bt * 16 + bRow) * 144 + ks * 32 + bHalf * 16);
                LDM4(bH[bt], sB + off);
            }
            #pragma unroll
            for (int mt = 0; mt < 4; mt++)
                #pragma unroll
                for (int nt = 0; nt < 4; nt++) {
                    const int bt = nt >> 1, p = (nt & 1) * 2;
                    MMA(acc[mt][nt], aH[mt], bH[bt][p], bH[bt][p + 1]);
                    MMA(acc[mt][nt], aL[mt], bH[bt][p], bH[bt][p + 1]);
                }
        }
    };

    load_stage(0, 0);
    for (int ic = 0; ic < nc; ic++) {
        if (ic + 1 < nc) { load_stage((ic + 1) & 1, (ic + 1) << 6); CP_WAIT(1); }
        else             { CP_WAIT(0); }
        __syncthreads();
        compute_stage(ic & 1);
        __syncthreads();
    }

    const int rowb = lane >> 2, colb = (lane & 3) * 2;
    #pragma unroll
    for (int mt = 0; mt < 4; mt++)
        #pragma unroll
        for (int nt = 0; nt < 4; nt++) {
            const int r = m0 + wm + mt * 16 + rowb;
            const int cI = n0 + wn + nt * 8 + colb;
            float v0 = acc[mt][nt][0], v1 = acc[mt][nt][1];
            float v2 = acc[mt][nt][2], v3 = acc[mt][nt][3];
            if (SPLIT_OUT) {
                *(uint32_t*)&Chi[(size_t)r * N + cI] = packh(v0, v1);
                *(uint32_t*)&Clo[(size_t)r * N + cI] = packh(v0 - hhi(v0), v1 - hhi(v1));
                *(uint32_t*)&Chi[(size_t)(r + 8) * N + cI] = packh(v2, v3);
                *(uint32_t*)&Clo[(size_t)(r + 8) * N + cI] = packh(v2 - hhi(v2), v3 - hhi(v3));
            } else {
                *(float2*)&C[(size_t)r * N + cI]       = make_float2(v0, v1);
                *(float2*)&C[(size_t)(r + 8) * N + cI] = make_float2(v2, v3);
            }
        }
}

// ---------------------------------------------------------------------------
// Tensor-core causal flash attention, fp16 2-term (Q,P split; K,V single).
// Q fragments hoisted to registers. CTA: 256 threads (8 warps), q-tile 128,
// k-tile 64, 2-stage cp.async KV pipeline. 73.7 KB smem -> 3 CTAs/SM.
// ---------------------------------------------------------------------------
#define FQ_BYTES 18432          // 128*144
#define FKV_MAT 9216            // 64*144
#define FSTAGE (2 * FKV_MAT)    // 18432 (Kh + Vh)
#define FSMEM (2 * FQ_BYTES + 2 * FSTAGE)   // 73728

__global__ __launch_bounds__(256) void flash_mma(
    const __half* __restrict__ qhi, const __half* __restrict__ qlo,
    __half* __restrict__ outhi, __half* __restrict__ outlo)
{
    extern __shared__ char smem[];
    const uint32_t sb = smem_u32(smem);
    const uint32_t sQh = sb, sQl = sb + FQ_BYTES;
    const uint32_t sStage = sb + 2 * FQ_BYTES;

    const int tid = threadIdx.x, wid = tid >> 5, lane = tid & 31;
    const int q0 = ((int)gridDim.x - 1 - (int)blockIdx.x) * 128;
    const int h = blockIdx.y, b = blockIdx.z;
    const int qrow0 = q0 + wid * 16;

    const __half* bhiP = qhi + (size_t)b * SLEN * D3 + h * HD;
    const __half* bloP = qlo + (size_t)b * SLEN * D3 + h * HD;

    const int rA = lane & 15, hA = lane >> 4;              // A frag (Q rows)
    const int qB = lane >> 3, r8 = lane & 7;               // B frag (K rows)
    const int bRow = (qB >> 1) * 8 + r8, bHalf = qB & 1;
    const int grp = lane >> 3, l8 = lane & 7;              // V trans frag

    // Stage Q tile (hi+lo): 2048 chunks
    {
        #pragma unroll
        for (int j = 0; j < 8; j++) {
            int idx = tid + j * 256;
            int mat = idx >> 10, row = (idx >> 3) & 127, c = idx & 7;
            const __half* src = (mat ? bloP : bhiP) + (size_t)(q0 + row) * D3 + c * 8;
            cp16((mat ? sQl : sQh) + (uint32_t)(row * 144 + c * 16), src);
        }
    }

    const int nk = q0 / 64 + 2;

    auto load_kv = [&](int st, int k0) {
        uint32_t base = sStage + (uint32_t)st * FSTAGE;
        #pragma unroll
        for (int j = 0; j < 4; j++) {   // Kh + Vh: 1024 chunks
            int idx = tid + j * 256;
            int mat = idx >> 9, row = (idx >> 3) & 63, c = idx & 7;
            int seg = mat ? 2 * DMODEL : DMODEL;   // 0=K, 1=V
            const __half* src = bhiP + (size_t)(k0 + row) * D3 + seg + c * 8;
            cp16(base + (uint32_t)mat * FKV_MAT + (uint32_t)(row * 144 + c * 16), src);
        }
        CP_COMMIT();
    };

    float oacc[8][4];
    #pragma unroll
    for (int i = 0; i < 8; i++)
        #pragma unroll
        for (int j = 0; j < 4; j++) oacc[i][j] = 0.f;
    float m0 = -1e30f, m1 = -1e30f, l0 = 0.f, l1 = 0.f;

    uint32_t qH[4][4], qL[4][4];   // hoisted Q fragments (per ks)

    load_kv(0, 0);
    CP_COMMIT();

    for (int it = 0; it < nk; it++) {
        const int k0 = it * 64;
        if (it + 1 < nk) { load_kv((it + 1) & 1, (it + 1) * 64); CP_WAIT(1); }
        else             { CP_WAIT(0); }
        __syncthreads();

        if (it == 0) {   // Q resident now; hoist frags once
            #pragma unroll
            for (int ks = 0; ks < 4; ks++) {
                uint32_t aoff = (uint32_t)((wid * 16 + rA) * 144 + ks * 32 + hA * 16);
                LDM4(qH[ks], sQh + aoff);
                LDM4(qL[ks], sQl + aoff);
            }
        }

        if (k0 <= qrow0 + 15) {
            const uint32_t st = sStage + (uint32_t)(it & 1) * FSTAGE;
            const uint32_t sKh = st, sVh = st + FKV_MAT;

            // ---- S = Q K^T (2-term), 16x64 per warp
            float sfrag[8][4];
            #pragma unroll
            for (int i = 0; i < 8; i++)
                #pragma unroll
                for (int j = 0; j < 4; j++) sfrag[i][j] = 0.f;

            #pragma unroll
            for (int ks = 0; ks < 4; ks++) {
                uint32_t kh[4][4];
                #pragma unroll
                for (int bt = 0; bt < 4; bt++) {
                    uint32_t off = (uint32_t)((bt * 16 + bRow) * 144 + ks * 32 + bHalf * 16);
                    LDM4(kh[bt], sKh + off);
                }
                #pragma unroll
                for (int nt = 0; nt < 8; nt++) {
                    const int bt = nt >> 1, p = (nt & 1) * 2;
                    MMA(sfrag[nt], qH[ks], kh[bt][p], kh[bt][p + 1]);
                    MMA(sfrag[nt], qL[ks], kh[bt][p], kh[bt][p + 1]);
                }
            }

            // ---- causal mask on diagonal tiles
            const int row0 = qrow0 + (lane >> 2), row1 = row0 + 8;
            if (k0 + 63 > qrow0) {
                #pragma unroll
                for (int nt = 0; nt < 8; nt++) {
                    int col = k0 + nt * 8 + ((lane & 3) << 1);
                    if (col > row0)     sfrag[nt][0] = -1e30f;
                    if (col + 1 > row0) sfrag[nt][1] = -1e30f;
                    if (col > row1)     sfrag[nt][2] = -1e30f;
                    if (col + 1 > row1) sfrag[nt][3] = -1e30f;
                }
            }

            // ---- online softmax
            float mc0 = -1e30f, mc1 = -1e30f;
            #pragma unroll
            for (int nt = 0; nt < 8; nt++) {
                mc0 = fmaxf(mc0, fmaxf(sfrag[nt][0], sfrag[nt][1]));
                mc1 = fmaxf(mc1, fmaxf(sfrag[nt][2], sfrag[nt][3]));
            }
            mc0 = fmaxf(mc0, __shfl_xor_sync(0xffffffffu, mc0, 1));
            mc0 = fmaxf(mc0, __shfl_xor_sync(0xffffffffu, mc0, 2));
            mc1 = fmaxf(mc1, __shfl_xor_sync(0xffffffffu, mc1, 1));
            mc1 = fmaxf(mc1, __shfl_xor_sync(0xffffffffu, mc1, 2));
            const float mn0 = fmaxf(m0, mc0), mn1 = fmaxf(m1, mc1);
            const float corr0 = exp2_fast((m0 - mn0) * CEXP);
            const float corr1 = exp2_fast((m1 - mn1) * CEXP);
            m0 = mn0; m1 = mn1;

            float rs0 = 0.f, rs1 = 0.f;
            #pragma unroll
            for (int nt = 0; nt < 8; nt++) {
                sfrag[nt][0] = exp2_fast((sfrag[nt][0] - mn0) * CEXP);
                sfrag[nt][1] = exp2_fast((sfrag[nt][1] - mn0) * CEXP);
                sfrag[nt][2] = exp2_fast((sfrag[nt][2] - mn1) * CEXP);
                sfrag[nt][3] = exp2_fast((sfrag[nt][3] - mn1) * CEXP);
                rs0 += sfrag[nt][0] + sfrag[nt][1];
                rs1 += sfrag[nt][2] + sfrag[nt][3];
            }
            rs0 += __shfl_xor_sync(0xffffffffu, rs0, 1);
            rs0 += __shfl_xor_sync(0xffffffffu, rs0, 2);
            rs1 += __shfl_xor_sync(0xffffffffu, rs1, 1);
            rs1 += __shfl_xor_sync(0xffffffffu, rs1, 2);
            l0 = l0 * corr0 + rs0;
            l1 = l1 * corr1 + rs1;
            #pragma unroll
            for (int nt = 0; nt < 8; nt++) {
                oacc[nt][0] *= corr0; oacc[nt][1] *= corr0;
                oacc[nt][2] *= corr1; oacc[nt][3] *= corr1;
            }

            // ---- O += P V (P split, V single)
            #pragma unroll
            for (int t = 0; t < 4; t++) {
                uint32_t phi[4], plo[4];
                {
                    float p0 = sfrag[2 * t][0], p1 = sfrag[2 * t][1];
                    float p2 = sfrag[2 * t][2], p3 = sfrag[2 * t][3];
                    float p4 = sfrag[2 * t + 1][0], p5 = sfrag[2 * t + 1][1];
                    float p6 = sfrag[2 * t + 1][2], p7 = sfrag[2 * t + 1][3];
                    phi[0] = packh(p0, p1); phi[1] = packh(p2, p3);
                    phi[2] = packh(p4, p5); phi[3] = packh(p6, p7);
                    plo[0] = packh(p0 - hhi(p0), p1 - hhi(p1));
                    plo[1] = packh(p2 - hhi(p2), p3 - hhi(p3));
                    plo[2] = packh(p4 - hhi(p4), p5 - hhi(p5));
                    plo[3] = packh(p6 - hhi(p6), p7 - hhi(p7));
                }
                #pragma unroll
                for (int np = 0; np < 4; np++) {
                    uint32_t vh[4];
                    uint32_t off = (uint32_t)((t * 16 + (grp & 1) * 8 + l8) * 144 +
                                              (np * 16 + (grp >> 1) * 8) * 2);
                    LDM4T(vh, sVh + off);
                    const int nt0 = np * 2;
                    MMA(oacc[nt0], phi, vh[0], vh[1]);
                    MMA(oacc[nt0], plo, vh[0], vh[1]);
                    MMA(oacc[nt0 + 1], phi, vh[2], vh[3]);
                    MMA(oacc[nt0 + 1], plo, vh[2], vh[3]);
                }
            }
        }
        __syncthreads();
    }

    // ---- finalize
    const float inv0 = 1.f / l0, inv1 = 1.f / l1;
    const int row0 = q0 + wid * 16 + (lane >> 2);
    const int colb = h * HD + (lane & 3) * 2;
    #pragma unroll
    for (int nt = 0; nt < 8; nt++) {
        float v0 = oacc[nt][0] * inv0, v1 = oacc[nt][1] * inv0;
        float v2 = oacc[nt][2] * inv1, v3 = oacc[nt][3] * inv1;
        size_t o0 = (size_t)(b * SLEN + row0) * DMODEL + colb + nt * 8;
        size_t o1 = (size_t)(b * SLEN + row0 + 8) * DMODEL + colb + nt * 8;
        *(uint32_t*)&outhi[o0] = packh(v0, v1);
        *(uint32_t*)&outlo[o0] = packh(v0 - hhi(v0), v1 - hhi(v1));
        *(uint32_t*)&outhi[o1] = packh(v2, v3);
        *(uint32_t*)&outlo[o1] = packh(v2 - hhi(v2), v3 - hhi(v3));
    }
}

// ---------------------------------------------------------------------------
// kernel_launch
// ---------------------------------------------------------------------------
extern "C" void kernel_launch(void* const* d_in, const int* in_sizes, int n_in,
                              void* d_out, int out_size)
{
    const float* x     = (const float*)d_in[0];
    const float* w_qkv = (const float*)d_in[1];
    const float* w_out = (const float*)d_in[2];
    float* out = (float*)d_out;

    __half *xhi, *xlo, *w1h, *w2h, *qhi, *qlo, *ahi, *alo;
    cudaGetSymbolAddress((void**)&xhi, g_xhi);
    cudaGetSymbolAddress((void**)&xlo, g_xlo);
    cudaGetSymbolAddress((void**)&w1h, g_w1h);
    cudaGetSymbolAddress((void**)&w2h, g_w2h);
    cudaGetSymbolAddress((void**)&qhi, g_qkvhi);
    cudaGetSymbolAddress((void**)&qlo, g_qkvlo);
    cudaGetSymbolAddress((void**)&ahi, g_ahi);
    cudaGetSymbolAddress((void**)&alo, g_alo);

    cudaFuncSetAttribute(gemm_mma2<0>, cudaFuncAttributeMaxDynamicSharedMemorySize, GSMEM_BYTES);
    cudaFuncSetAttribute(gemm_mma2<1>, cudaFuncAttributeMaxDynamicSharedMemorySize, GSMEM_BYTES);
    cudaFuncSetAttribute(flash_mma, cudaFuncAttributeMaxDynamicSharedMemorySize, FSMEM);

    const int M = MDIM;

    split_fp32<<<(M * DMODEL / 4 + 255) / 256, 256>>>(x, xhi, xlo, M * DMODEL / 4);
    transpose_h<<<dim3(D3 / 32, DMODEL / 32), dim3(32, 8)>>>(w_qkv, w1h, DMODEL, D3);
    transpose_h<<<dim3(DMODEL / 32, DMODEL / 32), dim3(32, 8)>>>(w_out, w2h, DMODEL, DMODEL);

    // 1) qkv (split fp16 out) = x @ w_qkv
    gemm_mma2<1><<<dim3(D3 / 128, M / 128), 256, GSMEM_BYTES>>>(
        xhi, xlo, w1h, nullptr, qhi, qlo, M, D3, DMODEL);

    // 2) tensor-core causal flash attention -> split fp16 att
    flash_mma<<<dim3(SLEN / 128, HEADS, BATCH), 256, FSMEM>>>(qhi, qlo, ahi, alo);

    // 3) out = att @ w_out (fp32 out)
    gemm_mma2<0><<<dim3(DMODEL / 128, M / 128), 256, GSMEM_BYTES>>>(
        ahi, alo, w2h, out, nullptr, nullptr, M, DMODEL, DMODEL);
}

// round 10
// speedup vs baseline: 1.6900x; 1.1985x over previous
#include <cuda_runtime.h>
#include <cuda_fp16.h>
#include <cstdint>

// Problem constants
#define BATCH 2
#define SLEN 2048
#define DMODEL 1024
#define HEADS 16
#define HD 64
#define MDIM (BATCH * SLEN)   // 4096
#define D3 (3 * DMODEL)       // 3072

// ---------------------------------------------------------------------------
// Scratch (device globals; no allocations allowed)
// ---------------------------------------------------------------------------
__device__ __half g_xh[(size_t)MDIM * DMODEL];
__device__ __half g_w1h[(size_t)D3 * DMODEL];      // w_qkv^T [3D, D]
__device__ __half g_w2h[(size_t)DMODEL * DMODEL];  // w_out^T [D, D]
__device__ __half g_qkvh[(size_t)MDIM * D3];       // GEMM1 fp16 output
__device__ __half g_ah[(size_t)MDIM * DMODEL];     // attention fp16 output

// ---------------------------------------------------------------------------
// PTX helpers (sm_80+ only — harness targets base sm_100)
// ---------------------------------------------------------------------------
__device__ __forceinline__ uint32_t smem_u32(const void* p) {
    uint32_t a;
    asm("{ .reg .u64 t; cvta.to.shared.u64 t, %1; cvt.u32.u64 %0, t; }" : "=r"(a) : "l"(p));
    return a;
}
__device__ __forceinline__ void cp16(uint32_t dst, const void* src) {
    asm volatile("cp.async.cg.shared.global [%0], [%1], 16;" :: "r"(dst), "l"(src) : "memory");
}
#define CP_COMMIT() asm volatile("cp.async.commit_group;" ::: "memory")
#define CP_WAIT(n)  asm volatile("cp.async.wait_group %0;" :: "n"(n) : "memory")

#define LDM4(r, addr) \
    asm volatile("ldmatrix.sync.aligned.m8n8.x4.shared.b16 {%0,%1,%2,%3}, [%4];" \
        : "=r"((r)[0]), "=r"((r)[1]), "=r"((r)[2]), "=r"((r)[3]) : "r"(addr))
#define LDM4T(r, addr) \
    asm volatile("ldmatrix.sync.aligned.m8n8.x4.trans.shared.b16 {%0,%1,%2,%3}, [%4];" \
        : "=r"((r)[0]), "=r"((r)[1]), "=r"((r)[2]), "=r"((r)[3]) : "r"(addr))

#define MMA(d, a, b0, b1) \
    asm volatile("mma.sync.aligned.m16n8k16.row.col.f32.f16.f16.f32 " \
        "{%0,%1,%2,%3}, {%4,%5,%6,%7}, {%8,%9}, {%0,%1,%2,%3};" \
        : "+f"((d)[0]), "+f"((d)[1]), "+f"((d)[2]), "+f"((d)[3]) \
        : "r"((a)[0]), "r"((a)[1]), "r"((a)[2]), "r"((a)[3]), "r"(b0), "r"(b1))

__device__ __forceinline__ uint32_t packh(float a, float b) {
    __half2 t = __floats2half2_rn(a, b);
    return *reinterpret_cast<uint32_t*>(&t);
}

// Fast exp2: deg-4 poly + exponent stuffing. x <= 0 expected; ~1e-6 rel err.
__device__ __forceinline__ float exp2_fast(float x) {
    x = fmaxf(x, -126.0f);
    int xi = __float2int_rd(x);
    float f = x - (float)xi;
    float p = 0.0135557472f;
    p = fmaf(p, f, 0.0520323690f);
    p = fmaf(p, f, 0.2413797743f);
    p = fmaf(p, f, 0.6930321187f);
    p = fmaf(p, f, 1.0f);
    return __int_as_float((xi + 127) << 23) * p;
}

#define CEXP 0.1803368801111204f   // 0.125 * log2(e)

// ---------------------------------------------------------------------------
// Cast fp32 -> fp16 elementwise (vectorized by 4)
// ---------------------------------------------------------------------------
__global__ __launch_bounds__(256) void cast_h(
    const float* __restrict__ src, __half* __restrict__ dst, int n4)
{
    int i = blockIdx.x * blockDim.x + threadIdx.x;
    if (i >= n4) return;
    float4 v = reinterpret_cast<const float4*>(src)[i];
    uint2 hp;
    hp.x = packh(v.x, v.y);
    hp.y = packh(v.z, v.w);
    reinterpret_cast<uint2*>(dst)[i] = hp;
}

// ---------------------------------------------------------------------------
// Transpose to fp16: src [R, C] fp32 -> hT [C, R] fp16
// ---------------------------------------------------------------------------
__global__ __launch_bounds__(256) void transpose_h(
    const float* __restrict__ src, __half* __restrict__ hT, int R, int C)
{
    __shared__ float t[32][33];
    const int c0 = blockIdx.x * 32, r0 = blockIdx.y * 32;
    const int tx = threadIdx.x, ty = threadIdx.y;   // 32 x 8
    #pragma unroll
    for (int j = 0; j < 4; j++)
        t[ty + 8 * j][tx] = src[(size_t)(r0 + ty + 8 * j) * C + c0 + tx];
    __syncthreads();
    #pragma unroll
    for (int j = 0; j < 4; j++)
        hT[(size_t)(c0 + ty + 8 * j) * R + r0 + tx] = __float2half_rn(t[tx][ty + 8 * j]);
}

// ---------------------------------------------------------------------------
// Warp-MMA fp16 GEMM. C[M,N] = A[M,K] @ BT[N,K]^T, fp32 accumulate.
// CTA tile 128x128, 256 threads (8 warps, 2Mx4N), warp tile 64x32.
// 2-stage cp.async, 73.7 KB smem -> 3 CTAs/SM.
// HALF_OUT=1: fp16 out; else fp32.
// ---------------------------------------------------------------------------
#define A_MAT 18432            // 128 rows * 144 B
#define STAGE_BYTES 36864      // A + B
#define GSMEM_BYTES 73728      // 2 stages

template<int HALF_OUT>
__global__ __launch_bounds__(256, 3) void gemm_h(
    const __half* __restrict__ A, const __half* __restrict__ BT,
    float* __restrict__ C, __half* __restrict__ Ch,
    int M, int N, int K)
{
    extern __shared__ char smem[];
    const uint32_t sb = smem_u32(smem);
    const int tid = threadIdx.x;
    const int wid = tid >> 5, lane = tid & 31;
    const int m0 = blockIdx.y << 7, n0 = blockIdx.x << 7;
    const int wm = (wid >> 2) * 64, wn = (wid & 3) * 32;
    const int nc = K >> 6;

    const __half* gA = A + (size_t)m0 * K;
    const __half* gB = BT + (size_t)n0 * K;

    float acc[4][4][4];
    #pragma unroll
    for (int a = 0; a < 4; a++)
        #pragma unroll
        for (int b = 0; b < 4; b++)
            #pragma unroll
            for (int c = 0; c < 4; c++) acc[a][b][c] = 0.f;

    const int rA = lane & 15, hA = lane >> 4;
    const int qB = lane >> 3, r8 = lane & 7;
    const int bRow = (qB >> 1) * 8 + r8, bHalf = qB & 1;

    auto load_stage = [&](int st, int kk) {
        uint32_t base = sb + (uint32_t)st * STAGE_BYTES;
        #pragma unroll
        for (int j = 0; j < 4; j++) {     // A: 1024 chunks
            int idx = tid + j * 256;
            int row = idx >> 3, c = idx & 7;
            cp16(base + (uint32_t)(row * 144 + c * 16), gA + kk + (size_t)row * K + c * 8);
        }
        #pragma unroll
        for (int j = 0; j < 4; j++) {     // B: 1024 chunks
            int idx = tid + j * 256;
            int row = idx >> 3, c = idx & 7;
            cp16(base + A_MAT + (uint32_t)(row * 144 + c * 16), gB + kk + (size_t)row * K + c * 8);
        }
        CP_COMMIT();
    };

    auto compute_stage = [&](int st) {
        uint32_t base = sb + (uint32_t)st * STAGE_BYTES;
        const uint32_t sA = base, sB = base + A_MAT;
        #pragma unroll
        for (int ks = 0; ks < 4; ks++) {
            uint32_t aF[4][4], bF[2][4];
            #pragma unroll
            for (int mt = 0; mt < 4; mt++) {
                uint32_t off = (uint32_t)((wm + mt * 16 + rA) * 144 + ks * 32 + hA * 16);
                LDM4(aF[mt], sA + off);
            }
            #pragma unroll
            for (int bt = 0; bt < 2; bt++) {
                uint32_t off = (uint32_t)((wn + bt * 16 + bRow) * 144 + ks * 32 + bHalf * 16);
                LDM4(bF[bt], sB + off);
            }
            #pragma unroll
            for (int mt = 0; mt < 4; mt++)
                #pragma unroll
                for (int nt = 0; nt < 4; nt++) {
                    const int bt = nt >> 1, p = (nt & 1) * 2;
                    MMA(acc[mt][nt], aF[mt], bF[bt][p], bF[bt][p + 1]);
                }
        }
    };

    load_stage(0, 0);
    for (int ic = 0; ic < nc; ic++) {
        if (ic + 1 < nc) { load_stage((ic + 1) & 1, (ic + 1) << 6); CP_WAIT(1); }
        else             { CP_WAIT(0); }
        __syncthreads();
        compute_stage(ic & 1);
        __syncthreads();
    }

    const int rowb = lane >> 2, colb = (lane & 3) * 2;
    #pragma unroll
    for (int mt = 0; mt < 4; mt++)
        #pragma unroll
        for (int nt = 0; nt < 4; nt++) {
            const int r = m0 + wm + mt * 16 + rowb;
            const int cI = n0 + wn + nt * 8 + colb;
            float v0 = acc[mt][nt][0], v1 = acc[mt][nt][1];
            float v2 = acc[mt][nt][2], v3 = acc[mt][nt][3];
            if (HALF_OUT) {
                *(uint32_t*)&Ch[(size_t)r * N + cI]       = packh(v0, v1);
                *(uint32_t*)&Ch[(size_t)(r + 8) * N + cI] = packh(v2, v3);
            } else {
                *(float2*)&C[(size_t)r * N + cI]       = make_float2(v0, v1);
                *(float2*)&C[(size_t)(r + 8) * N + cI] = make_float2(v2, v3);
            }
        }
}

// ---------------------------------------------------------------------------
// Tensor-core causal flash attention, pure fp16 operands, fp32 accum/softmax.
// Q fragments hoisted to registers. CTA: 256 threads (8 warps), q-tile 128,
// k-tile 64, 2-stage cp.async KV pipeline. 55.3 KB smem -> 4 CTAs/SM.
// ---------------------------------------------------------------------------
#define FQ_BYTES 18432          // 128*144
#define FKV_MAT 9216            // 64*144
#define FSTAGE (2 * FKV_MAT)    // 18432 (K + V)
#define FSMEM (FQ_BYTES + 2 * FSTAGE)   // 55296

__global__ __launch_bounds__(256) void flash_mma(
    const __half* __restrict__ qkv, __half* __restrict__ outh)
{
    extern __shared__ char smem[];
    const uint32_t sb = smem_u32(smem);
    const uint32_t sQ = sb;
    const uint32_t sStage = sb + FQ_BYTES;

    const int tid = threadIdx.x, wid = tid >> 5, lane = tid & 31;
    const int q0 = ((int)gridDim.x - 1 - (int)blockIdx.x) * 128;
    const int h = blockIdx.y, b = blockIdx.z;
    const int qrow0 = q0 + wid * 16;

    const __half* baseP = qkv + (size_t)b * SLEN * D3 + h * HD;

    const int rA = lane & 15, hA = lane >> 4;              // A frag (Q rows)
    const int qB = lane >> 3, r8 = lane & 7;               // B frag (K rows)
    const int bRow = (qB >> 1) * 8 + r8, bHalf = qB & 1;
    const int grp = lane >> 3, l8 = lane & 7;              // V trans frag

    // Stage Q tile: 1024 chunks
    {
        #pragma unroll
        for (int j = 0; j < 4; j++) {
            int idx = tid + j * 256;
            int row = idx >> 3, c = idx & 7;
            cp16(sQ + (uint32_t)(row * 144 + c * 16),
                 baseP + (size_t)(q0 + row) * D3 + c * 8);
        }
    }

    const int nk = q0 / 64 + 2;

    auto load_kv = [&](int st, int k0) {
        uint32_t base = sStage + (uint32_t)st * FSTAGE;
        #pragma unroll
        for (int j = 0; j < 4; j++) {   // K + V: 1024 chunks
            int idx = tid + j * 256;
            int mat = idx >> 9, row = (idx >> 3) & 63, c = idx & 7;
            int seg = mat ? 2 * DMODEL : DMODEL;   // 0=K, 1=V
            cp16(base + (uint32_t)mat * FKV_MAT + (uint32_t)(row * 144 + c * 16),
                 baseP + (size_t)(k0 + row) * D3 + seg + c * 8);
        }
        CP_COMMIT();
    };

    float oacc[8][4];
    #pragma unroll
    for (int i = 0; i < 8; i++)
        #pragma unroll
        for (int j = 0; j < 4; j++) oacc[i][j] = 0.f;
    float m0 = -1e30f, m1 = -1e30f, l0 = 0.f, l1 = 0.f;

    uint32_t qF[4][4];   // hoisted Q fragments (per ks)

    load_kv(0, 0);
    CP_COMMIT();

    for (int it = 0; it < nk; it++) {
        const int k0 = it * 64;
        if (it + 1 < nk) { load_kv((it + 1) & 1, (it + 1) * 64); CP_WAIT(1); }
        else             { CP_WAIT(0); }
        __syncthreads();

        if (it == 0) {   // Q resident now; hoist frags once
            #pragma unroll
            for (int ks = 0; ks < 4; ks++) {
                uint32_t aoff = (uint32_t)((wid * 16 + rA) * 144 + ks * 32 + hA * 16);
                LDM4(qF[ks], sQ + aoff);
            }
        }

        if (k0 <= qrow0 + 15) {
            const uint32_t st = sStage + (uint32_t)(it & 1) * FSTAGE;
            const uint32_t sK = st, sV = st + FKV_MAT;

            // ---- S = Q K^T, 16x64 per warp
            float sfrag[8][4];
            #pragma unroll
            for (int i = 0; i < 8; i++)
                #pragma unroll
                for (int j = 0; j < 4; j++) sfrag[i][j] = 0.f;

            #pragma unroll
            for (int ks = 0; ks < 4; ks++) {
                uint32_t kF[4][4];
                #pragma unroll
                for (int bt = 0; bt < 4; bt++) {
                    uint32_t off = (uint32_t)((bt * 16 + bRow) * 144 + ks * 32 + bHalf * 16);
                    LDM4(kF[bt], sK + off);
                }
                #pragma unroll
                for (int nt = 0; nt < 8; nt++) {
                    const int bt = nt >> 1, p = (nt & 1) * 2;
                    MMA(sfrag[nt], qF[ks], kF[bt][p], kF[bt][p + 1]);
                }
            }

            // ---- causal mask on diagonal tiles
            const int row0 = qrow0 + (lane >> 2), row1 = row0 + 8;
            if (k0 + 63 > qrow0) {
                #pragma unroll
                for (int nt = 0; nt < 8; nt++) {
                    int col = k0 + nt * 8 + ((lane & 3) << 1);
                    if (col > row0)     sfrag[nt][0] = -1e30f;
                    if (col + 1 > row0) sfrag[nt][1] = -1e30f;
                    if (col > row1)     sfrag[nt][2] = -1e30f;
                    if (col + 1 > row1) sfrag[nt][3] = -1e30f;
                }
            }

            // ---- online softmax
            float mc0 = -1e30f, mc1 = -1e30f;
            #pragma unroll
            for (int nt = 0; nt < 8; nt++) {
                mc0 = fmaxf(mc0, fmaxf(sfrag[nt][0], sfrag[nt][1]));
                mc1 = fmaxf(mc1, fmaxf(sfrag[nt][2], sfrag[nt][3]));
            }
            mc0 = fmaxf(mc0, __shfl_xor_sync(0xffffffffu, mc0, 1));
            mc0 = fmaxf(mc0, __shfl_xor_sync(0xffffffffu, mc0, 2));
            mc1 = fmaxf(mc1, __shfl_xor_sync(0xffffffffu, mc1, 1));
            mc1 = fmaxf(mc1, __shfl_xor_sync(0xffffffffu, mc1, 2));
            const float mn0 = fmaxf(m0, mc0), mn1 = fmaxf(m1, mc1);
            const float corr0 = exp2_fast((m0 - mn0) * CEXP);
            const float corr1 = exp2_fast((m1 - mn1) * CEXP);
            m0 = mn0; m1 = mn1;

            float rs0 = 0.f, rs1 = 0.f;
            #pragma unroll
            for (int nt = 0; nt < 8; nt++) {
                sfrag[nt][0] = exp2_fast((sfrag[nt][0] - mn0) * CEXP);
                sfrag[nt][1] = exp2_fast((sfrag[nt][1] - mn0) * CEXP);
                sfrag[nt][2] = exp2_fast((sfrag[nt][2] - mn1) * CEXP);
                sfrag[nt][3] = exp2_fast((sfrag[nt][3] - mn1) * CEXP);
                rs0 += sfrag[nt][0] + sfrag[nt][1];
                rs1 += sfrag[nt][2] + sfrag[nt][3];
            }
            rs0 += __shfl_xor_sync(0xffffffffu, rs0, 1);
            rs0 += __shfl_xor_sync(0xffffffffu, rs0, 2);
            rs1 += __shfl_xor_sync(0xffffffffu, rs1, 1);
            rs1 += __shfl_xor_sync(0xffffffffu, rs1, 2);
            l0 = l0 * corr0 + rs0;
            l1 = l1 * corr1 + rs1;
            #pragma unroll
            for (int nt = 0; nt < 8; nt++) {
                oacc[nt][0] *= corr0; oacc[nt][1] *= corr0;
                oacc[nt][2] *= corr1; oacc[nt][3] *= corr1;
            }

            // ---- O += P V (single fp16 P and V)
            #pragma unroll
            for (int t = 0; t < 4; t++) {
                uint32_t pF[4];
                pF[0] = packh(sfrag[2 * t][0], sfrag[2 * t][1]);
                pF[1] = packh(sfrag[2 * t][2], sfrag[2 * t][3]);
                pF[2] = packh(sfrag[2 * t + 1][0], sfrag[2 * t + 1][1]);
                pF[3] = packh(sfrag[2 * t + 1][2], sfrag[2 * t + 1][3]);
                #pragma unroll
                for (int np = 0; np < 4; np++) {
                    uint32_t vF[4];
                    uint32_t off = (uint32_t)((t * 16 + (grp & 1) * 8 + l8) * 144 +
                                              (np * 16 + (grp >> 1) * 8) * 2);
                    LDM4T(vF, sV + off);
                    MMA(oacc[np * 2],     pF, vF[0], vF[1]);
                    MMA(oacc[np * 2 + 1], pF, vF[2], vF[3]);
                }
            }
        }
        __syncthreads();
    }

    // ---- finalize: O /= l, write fp16 output [B*S, D]
    const float inv0 = 1.f / l0, inv1 = 1.f / l1;
    const int row0 = q0 + wid * 16 + (lane >> 2);
    const int colb = h * HD + (lane & 3) * 2;
    #pragma unroll
    for (int nt = 0; nt < 8; nt++) {
        float v0 = oacc[nt][0] * inv0, v1 = oacc[nt][1] * inv0;
        float v2 = oacc[nt][2] * inv1, v3 = oacc[nt][3] * inv1;
        size_t o0 = (size_t)(b * SLEN + row0) * DMODEL + colb + nt * 8;
        size_t o1 = (size_t)(b * SLEN + row0 + 8) * DMODEL + colb + nt * 8;
        *(uint32_t*)&outh[o0] = packh(v0, v1);
        *(uint32_t*)&outh[o1] = packh(v2, v3);
    }
}

// ---------------------------------------------------------------------------
// kernel_launch
// ---------------------------------------------------------------------------
extern "C" void kernel_launch(void* const* d_in, const int* in_sizes, int n_in,
                              void* d_out, int out_size)
{
    const float* x     = (const float*)d_in[0];
    const float* w_qkv = (const float*)d_in[1];
    const float* w_out = (const float*)d_in[2];
    float* out = (float*)d_out;

    __half *xh, *w1h, *w2h, *qh, *ah;
    cudaGetSymbolAddress((void**)&xh, g_xh);
    cudaGetSymbolAddress((void**)&w1h, g_w1h);
    cudaGetSymbolAddress((void**)&w2h, g_w2h);
    cudaGetSymbolAddress((void**)&qh, g_qkvh);
    cudaGetSymbolAddress((void**)&ah, g_ah);

    cudaFuncSetAttribute(gemm_h<0>, cudaFuncAttributeMaxDynamicSharedMemorySize, GSMEM_BYTES);
    cudaFuncSetAttribute(gemm_h<1>, cudaFuncAttributeMaxDynamicSharedMemorySize, GSMEM_BYTES);
    cudaFuncSetAttribute(flash_mma, cudaFuncAttributeMaxDynamicSharedMemorySize, FSMEM);

    const int M = MDIM;

    cast_h<<<(M * DMODEL / 4 + 255) / 256, 256>>>(x, xh, M * DMODEL / 4);
    transpose_h<<<dim3(D3 / 32, DMODEL / 32), dim3(32, 8)>>>(w_qkv, w1h, DMODEL, D3);
    transpose_h<<<dim3(DMODEL / 32, DMODEL / 32), dim3(32, 8)>>>(w_out, w2h, DMODEL, DMODEL);

    // 1) qkv (fp16) = x @ w_qkv
    gemm_h<1><<<dim3(D3 / 128, M / 128), 256, GSMEM_BYTES>>>(
        xh, w1h, nullptr, qh, M, D3, DMODEL);

    // 2) tensor-core causal flash attention -> fp16 att
    flash_mma<<<dim3(SLEN / 128, HEADS, BATCH), 256, FSMEM>>>(qh, ah);

    // 3) out = att @ w_out (fp32 out)
    gemm_h<0><<<dim3(DMODEL / 128, M / 128), 256, GSMEM_BYTES>>>(
        ah, w2h, out, nullptr, M, DMODEL, DMODEL);
}

// round 11
// speedup vs baseline: 2.2169x; 1.3118x over previous
#include <cuda_runtime.h>
#include <cuda_fp16.h>
#include <cstdint>

// Problem constants
#define BATCH 2
#define SLEN 2048
#define DMODEL 1024
#define HEADS 16
#define HD 64
#define MDIM (BATCH * SLEN)   // 4096
#define D3 (3 * DMODEL)       // 3072

// ---------------------------------------------------------------------------
// Scratch (device globals; no allocations allowed)
// ---------------------------------------------------------------------------
__device__ __half g_xh[(size_t)MDIM * DMODEL];
__device__ __half g_w1h[(size_t)D3 * DMODEL];      // w_qkv^T [3D, D]
__device__ __half g_w2h[(size_t)DMODEL * DMODEL];  // w_out^T [D, D]
__device__ __half g_qkvh[(size_t)MDIM * D3];       // GEMM1 fp16 output
__device__ __half g_ah[(size_t)MDIM * DMODEL];     // attention fp16 output

// ---------------------------------------------------------------------------
// PTX helpers (sm_80+ only — harness targets base sm_100)
// ---------------------------------------------------------------------------
__device__ __forceinline__ uint32_t smem_u32(const void* p) {
    uint32_t a;
    asm("{ .reg .u64 t; cvta.to.shared.u64 t, %1; cvt.u32.u64 %0, t; }" : "=r"(a) : "l"(p));
    return a;
}
__device__ __forceinline__ void cp16(uint32_t dst, const void* src) {
    asm volatile("cp.async.cg.shared.global [%0], [%1], 16;" :: "r"(dst), "l"(src) : "memory");
}
#define CP_COMMIT() asm volatile("cp.async.commit_group;" ::: "memory")
#define CP_WAIT(n)  asm volatile("cp.async.wait_group %0;" :: "n"(n) : "memory")

#define LDM4(r, addr) \
    asm volatile("ldmatrix.sync.aligned.m8n8.x4.shared.b16 {%0,%1,%2,%3}, [%4];" \
        : "=r"((r)[0]), "=r"((r)[1]), "=r"((r)[2]), "=r"((r)[3]) : "r"(addr))
#define LDM4T(r, addr) \
    asm volatile("ldmatrix.sync.aligned.m8n8.x4.trans.shared.b16 {%0,%1,%2,%3}, [%4];" \
        : "=r"((r)[0]), "=r"((r)[1]), "=r"((r)[2]), "=r"((r)[3]) : "r"(addr))

#define MMA(d, a, b0, b1) \
    asm volatile("mma.sync.aligned.m16n8k16.row.col.f32.f16.f16.f32 " \
        "{%0,%1,%2,%3}, {%4,%5,%6,%7}, {%8,%9}, {%0,%1,%2,%3};" \
        : "+f"((d)[0]), "+f"((d)[1]), "+f"((d)[2]), "+f"((d)[3]) \
        : "r"((a)[0]), "r"((a)[1]), "r"((a)[2]), "r"((a)[3]), "r"(b0), "r"(b1))

__device__ __forceinline__ uint32_t packh(float a, float b) {
    __half2 t = __floats2half2_rn(a, b);
    return *reinterpret_cast<uint32_t*>(&t);
}

// Fast exp2: deg-4 poly + exponent stuffing. x <= 0 expected; ~1e-6 rel err.
__device__ __forceinline__ float exp2_fast(float x) {
    x = fmaxf(x, -126.0f);
    int xi = __float2int_rd(x);
    float f = x - (float)xi;
    float p = 0.0135557472f;
    p = fmaf(p, f, 0.0520323690f);
    p = fmaf(p, f, 0.2413797743f);
    p = fmaf(p, f, 0.6930321187f);
    p = fmaf(p, f, 1.0f);
    return __int_as_float((xi + 127) << 23) * p;
}

#define CEXP 0.1803368801111204f   // 0.125 * log2(e)

// ---------------------------------------------------------------------------
// Cast fp32 -> fp16 elementwise (vectorized by 4)
// ---------------------------------------------------------------------------
__global__ __launch_bounds__(256) void cast_h(
    const float* __restrict__ src, __half* __restrict__ dst, int n4)
{
    int i = blockIdx.x * blockDim.x + threadIdx.x;
    if (i >= n4) return;
    float4 v = reinterpret_cast<const float4*>(src)[i];
    uint2 hp;
    hp.x = packh(v.x, v.y);
    hp.y = packh(v.z, v.w);
    reinterpret_cast<uint2*>(dst)[i] = hp;
}

// ---------------------------------------------------------------------------
// Transpose to fp16: src [R, C] fp32 -> hT [C, R] fp16
// ---------------------------------------------------------------------------
__global__ __launch_bounds__(256) void transpose_h(
    const float* __restrict__ src, __half* __restrict__ hT, int R, int C)
{
    __shared__ float t[32][33];
    const int c0 = blockIdx.x * 32, r0 = blockIdx.y * 32;
    const int tx = threadIdx.x, ty = threadIdx.y;   // 32 x 8
    #pragma unroll
    for (int j = 0; j < 4; j++)
        t[ty + 8 * j][tx] = src[(size_t)(r0 + ty + 8 * j) * C + c0 + tx];
    __syncthreads();
    #pragma unroll
    for (int j = 0; j < 4; j++)
        hT[(size_t)(c0 + ty + 8 * j) * R + r0 + tx] = __float2half_rn(t[tx][ty + 8 * j]);
}

// ---------------------------------------------------------------------------
// Warp-MMA fp16 GEMM. C[M,N] = A[M,K] @ BT[N,K]^T, fp32 accumulate.
// CTA tile 128x128, 256 threads (8 warps, 2Mx4N), warp tile 64x32.
// 3-stage cp.async pipeline, ONE __syncthreads per chunk.
// 110.6 KB smem -> 2 CTAs/SM. HALF_OUT=1: fp16 out; else fp32.
// ---------------------------------------------------------------------------
#define A_MAT 18432            // 128 rows * 144 B
#define STAGE_BYTES 36864      // A + B
#define GSMEM_BYTES 110592     // 3 stages

template<int HALF_OUT>
__global__ __launch_bounds__(256, 2) void gemm_h(
    const __half* __restrict__ A, const __half* __restrict__ BT,
    float* __restrict__ C, __half* __restrict__ Ch,
    int M, int N, int K)
{
    extern __shared__ char smem[];
    const uint32_t sb = smem_u32(smem);
    const int tid = threadIdx.x;
    const int wid = tid >> 5, lane = tid & 31;
    const int m0 = blockIdx.y << 7, n0 = blockIdx.x << 7;
    const int wm = (wid >> 2) * 64, wn = (wid & 3) * 32;
    const int nc = K >> 6;

    const __half* gA = A + (size_t)m0 * K;
    const __half* gB = BT + (size_t)n0 * K;

    float acc[4][4][4];
    #pragma unroll
    for (int a = 0; a < 4; a++)
        #pragma unroll
        for (int b = 0; b < 4; b++)
            #pragma unroll
            for (int c = 0; c < 4; c++) acc[a][b][c] = 0.f;

    const int rA = lane & 15, hA = lane >> 4;
    const int qB = lane >> 3, r8 = lane & 7;
    const int bRow = (qB >> 1) * 8 + r8, bHalf = qB & 1;

    auto load_stage = [&](int st, int kk) {
        uint32_t base = sb + (uint32_t)st * STAGE_BYTES;
        #pragma unroll
        for (int j = 0; j < 4; j++) {     // A: 1024 chunks
            int idx = tid + j * 256;
            int row = idx >> 3, c = idx & 7;
            cp16(base + (uint32_t)(row * 144 + c * 16), gA + kk + (size_t)row * K + c * 8);
        }
        #pragma unroll
        for (int j = 0; j < 4; j++) {     // B: 1024 chunks
            int idx = tid + j * 256;
            int row = idx >> 3, c = idx & 7;
            cp16(base + A_MAT + (uint32_t)(row * 144 + c * 16), gB + kk + (size_t)row * K + c * 8);
        }
        CP_COMMIT();
    };

    auto compute_stage = [&](int st) {
        uint32_t base = sb + (uint32_t)st * STAGE_BYTES;
        const uint32_t sA = base, sB = base + A_MAT;
        #pragma unroll
        for (int ks = 0; ks < 4; ks++) {
            uint32_t aF[4][4], bF[2][4];
            #pragma unroll
            for (int mt = 0; mt < 4; mt++) {
                uint32_t off = (uint32_t)((wm + mt * 16 + rA) * 144 + ks * 32 + hA * 16);
                LDM4(aF[mt], sA + off);
            }
            #pragma unroll
            for (int bt = 0; bt < 2; bt++) {
                uint32_t off = (uint32_t)((wn + bt * 16 + bRow) * 144 + ks * 32 + bHalf * 16);
                LDM4(bF[bt], sB + off);
            }
            #pragma unroll
            for (int mt = 0; mt < 4; mt++)
                #pragma unroll
                for (int nt = 0; nt < 4; nt++) {
                    const int bt = nt >> 1, p = (nt & 1) * 2;
                    MMA(acc[mt][nt], aF[mt], bF[bt][p], bF[bt][p + 1]);
                }
        }
    };

    // 3-stage pipeline, one barrier per chunk.
    load_stage(0, 0);
    load_stage(1, 64);
    int sc = 0;                 // compute stage index (mod 3)
    for (int ic = 0; ic < nc; ic++) {
        // Ensure chunk ic's loads are complete (pending after ic: at most ic+1).
        if (ic + 1 < nc) { CP_WAIT(1); } else { CP_WAIT(0); }
        __syncthreads();        // visibility + all warps done with stage (ic-1)%3
        if (ic + 2 < nc) {
            int sld = sc + 2 >= 3 ? sc - 1 : sc + 2;
            load_stage(sld, (ic + 2) << 6);
        }
        compute_stage(sc);
        sc = (sc + 1 == 3) ? 0 : sc + 1;
    }

    const int rowb = lane >> 2, colb = (lane & 3) * 2;
    #pragma unroll
    for (int mt = 0; mt < 4; mt++)
        #pragma unroll
        for (int nt = 0; nt < 4; nt++) {
            const int r = m0 + wm + mt * 16 + rowb;
            const int cI = n0 + wn + nt * 8 + colb;
            float v0 = acc[mt][nt][0], v1 = acc[mt][nt][1];
            float v2 = acc[mt][nt][2], v3 = acc[mt][nt][3];
            if (HALF_OUT) {
                *(uint32_t*)&Ch[(size_t)r * N + cI]       = packh(v0, v1);
                *(uint32_t*)&Ch[(size_t)(r + 8) * N + cI] = packh(v2, v3);
            } else {
                *(float2*)&C[(size_t)r * N + cI]       = make_float2(v0, v1);
                *(float2*)&C[(size_t)(r + 8) * N + cI] = make_float2(v2, v3);
            }
        }
}

// ---------------------------------------------------------------------------
// Tensor-core causal flash attention, pure fp16 operands, fp32 accum/softmax.
// Q fragments hoisted to registers. CTA: 256 threads (8 warps), q-tile 128,
// k-tile 64, 2-stage cp.async KV pipeline. 55.3 KB smem -> 4 CTAs/SM.
// ---------------------------------------------------------------------------
#define FQ_BYTES 18432          // 128*144
#define FKV_MAT 9216            // 64*144
#define FSTAGE (2 * FKV_MAT)    // 18432 (K + V)
#define FSMEM (FQ_BYTES + 2 * FSTAGE)   // 55296

__global__ __launch_bounds__(256) void flash_mma(
    const __half* __restrict__ qkv, __half* __restrict__ outh)
{
    extern __shared__ char smem[];
    const uint32_t sb = smem_u32(smem);
    const uint32_t sQ = sb;
    const uint32_t sStage = sb + FQ_BYTES;

    const int tid = threadIdx.x, wid = tid >> 5, lane = tid & 31;
    const int q0 = ((int)gridDim.x - 1 - (int)blockIdx.x) * 128;
    const int h = blockIdx.y, b = blockIdx.z;
    const int qrow0 = q0 + wid * 16;

    const __half* baseP = qkv + (size_t)b * SLEN * D3 + h * HD;

    const int rA = lane & 15, hA = lane >> 4;              // A frag (Q rows)
    const int qB = lane >> 3, r8 = lane & 7;               // B frag (K rows)
    const int bRow = (qB >> 1) * 8 + r8, bHalf = qB & 1;
    const int grp = lane >> 3, l8 = lane & 7;              // V trans frag

    // Stage Q tile: 1024 chunks
    {
        #pragma unroll
        for (int j = 0; j < 4; j++) {
            int idx = tid + j * 256;
            int row = idx >> 3, c = idx & 7;
            cp16(sQ + (uint32_t)(row * 144 + c * 16),
                 baseP + (size_t)(q0 + row) * D3 + c * 8);
        }
    }

    const int nk = q0 / 64 + 2;

    auto load_kv = [&](int st, int k0) {
        uint32_t base = sStage + (uint32_t)st * FSTAGE;
        #pragma unroll
        for (int j = 0; j < 4; j++) {   // K + V: 1024 chunks
            int idx = tid + j * 256;
            int mat = idx >> 9, row = (idx >> 3) & 63, c = idx & 7;
            int seg = mat ? 2 * DMODEL : DMODEL;   // 0=K, 1=V
            cp16(base + (uint32_t)mat * FKV_MAT + (uint32_t)(row * 144 + c * 16),
                 baseP + (size_t)(k0 + row) * D3 + seg + c * 8);
        }
        CP_COMMIT();
    };

    float oacc[8][4];
    #pragma unroll
    for (int i = 0; i < 8; i++)
        #pragma unroll
        for (int j = 0; j < 4; j++) oacc[i][j] = 0.f;
    float m0 = -1e30f, m1 = -1e30f, l0 = 0.f, l1 = 0.f;

    uint32_t qF[4][4];   // hoisted Q fragments (per ks)

    load_kv(0, 0);
    CP_COMMIT();

    for (int it = 0; it < nk; it++) {
        const int k0 = it * 64;
        if (it + 1 < nk) { load_kv((it + 1) & 1, (it + 1) * 64); CP_WAIT(1); }
        else             { CP_WAIT(0); }
        __syncthreads();

        if (it == 0) {   // Q resident now; hoist frags once
            #pragma unroll
            for (int ks = 0; ks < 4; ks++) {
                uint32_t aoff = (uint32_t)((wid * 16 + rA) * 144 + ks * 32 + hA * 16);
                LDM4(qF[ks], sQ + aoff);
            }
        }

        if (k0 <= qrow0 + 15) {
            const uint32_t st = sStage + (uint32_t)(it & 1) * FSTAGE;
            const uint32_t sK = st, sV = st + FKV_MAT;

            // ---- S = Q K^T, 16x64 per warp
            float sfrag[8][4];
            #pragma unroll
            for (int i = 0; i < 8; i++)
                #pragma unroll
                for (int j = 0; j < 4; j++) sfrag[i][j] = 0.f;

            #pragma unroll
            for (int ks = 0; ks < 4; ks++) {
                uint32_t kF[4][4];
                #pragma unroll
                for (int bt = 0; bt < 4; bt++) {
                    uint32_t off = (uint32_t)((bt * 16 + bRow) * 144 + ks * 32 + bHalf * 16);
                    LDM4(kF[bt], sK + off);
                }
                #pragma unroll
                for (int nt = 0; nt < 8; nt++) {
                    const int bt = nt >> 1, p = (nt & 1) * 2;
                    MMA(sfrag[nt], qF[ks], kF[bt][p], kF[bt][p + 1]);
                }
            }

            // ---- causal mask on diagonal tiles
            const int row0 = qrow0 + (lane >> 2), row1 = row0 + 8;
            if (k0 + 63 > qrow0) {
                #pragma unroll
                for (int nt = 0; nt < 8; nt++) {
                    int col = k0 + nt * 8 + ((lane & 3) << 1);
                    if (col > row0)     sfrag[nt][0] = -1e30f;
                    if (col + 1 > row0) sfrag[nt][1] = -1e30f;
                    if (col > row1)     sfrag[nt][2] = -1e30f;
                    if (col + 1 > row1) sfrag[nt][3] = -1e30f;
                }
            }

            // ---- online softmax
            float mc0 = -1e30f, mc1 = -1e30f;
            #pragma unroll
            for (int nt = 0; nt < 8; nt++) {
                mc0 = fmaxf(mc0, fmaxf(sfrag[nt][0], sfrag[nt][1]));
                mc1 = fmaxf(mc1, fmaxf(sfrag[nt][2], sfrag[nt][3]));
            }
            mc0 = fmaxf(mc0, __shfl_xor_sync(0xffffffffu, mc0, 1));
            mc0 = fmaxf(mc0, __shfl_xor_sync(0xffffffffu, mc0, 2));
            mc1 = fmaxf(mc1, __shfl_xor_sync(0xffffffffu, mc1, 1));
            mc1 = fmaxf(mc1, __shfl_xor_sync(0xffffffffu, mc1, 2));
            const float mn0 = fmaxf(m0, mc0), mn1 = fmaxf(m1, mc1);
            const float corr0 = exp2_fast((m0 - mn0) * CEXP);
            const float corr1 = exp2_fast((m1 - mn1) * CEXP);
            m0 = mn0; m1 = mn1;

            float rs0 = 0.f, rs1 = 0.f;
            #pragma unroll
            for (int nt = 0; nt < 8; nt++) {
                sfrag[nt][0] = exp2_fast((sfrag[nt][0] - mn0) * CEXP);
                sfrag[nt][1] = exp2_fast((sfrag[nt][1] - mn0) * CEXP);
                sfrag[nt][2] = exp2_fast((sfrag[nt][2] - mn1) * CEXP);
                sfrag[nt][3] = exp2_fast((sfrag[nt][3] - mn1) * CEXP);
                rs0 += sfrag[nt][0] + sfrag[nt][1];
                rs1 += sfrag[nt][2] + sfrag[nt][3];
            }
            rs0 += __shfl_xor_sync(0xffffffffu, rs0, 1);
            rs0 += __shfl_xor_sync(0xffffffffu, rs0, 2);
            rs1 += __shfl_xor_sync(0xffffffffu, rs1, 1);
            rs1 += __shfl_xor_sync(0xffffffffu, rs1, 2);
            l0 = l0 * corr0 + rs0;
            l1 = l1 * corr1 + rs1;
            #pragma unroll
            for (int nt = 0; nt < 8; nt++) {
                oacc[nt][0] *= corr0; oacc[nt][1] *= corr0;
                oacc[nt][2] *= corr1; oacc[nt][3] *= corr1;
            }

            // ---- O += P V (single fp16 P and V)
            #pragma unroll
            for (int t = 0; t < 4; t++) {
                uint32_t pF[4];
                pF[0] = packh(sfrag[2 * t][0], sfrag[2 * t][1]);
                pF[1] = packh(sfrag[2 * t][2], sfrag[2 * t][3]);
                pF[2] = packh(sfrag[2 * t + 1][0], sfrag[2 * t + 1][1]);
                pF[3] = packh(sfrag[2 * t + 1][2], sfrag[2 * t + 1][3]);
                #pragma unroll
                for (int np = 0; np < 4; np++) {
                    uint32_t vF[4];
                    uint32_t off = (uint32_t)((t * 16 + (grp & 1) * 8 + l8) * 144 +
                                              (np * 16 + (grp >> 1) * 8) * 2);
                    LDM4T(vF, sV + off);
                    MMA(oacc[np * 2],     pF, vF[0], vF[1]);
                    MMA(oacc[np * 2 + 1], pF, vF[2], vF[3]);
                }
            }
        }
        __syncthreads();
    }

    // ---- finalize: O /= l, write fp16 output [B*S, D]
    const float inv0 = 1.f / l0, inv1 = 1.f / l1;
    const int row0 = q0 + wid * 16 + (lane >> 2);
    const int colb = h * HD + (lane & 3) * 2;
    #pragma unroll
    for (int nt = 0; nt < 8; nt++) {
        float v0 = oacc[nt][0] * inv0, v1 = oacc[nt][1] * inv0;
        float v2 = oacc[nt][2] * inv1, v3 = oacc[nt][3] * inv1;
        size_t o0 = (size_t)(b * SLEN + row0) * DMODEL + colb + nt * 8;
        size_t o1 = (size_t)(b * SLEN + row0 + 8) * DMODEL + colb + nt * 8;
        *(uint32_t*)&outh[o0] = packh(v0, v1);
        *(uint32_t*)&outh[o1] = packh(v2, v3);
    }
}

// ---------------------------------------------------------------------------
// kernel_launch
// ---------------------------------------------------------------------------
extern "C" void kernel_launch(void* const* d_in, const int* in_sizes, int n_in,
                              void* d_out, int out_size)
{
    const float* x     = (const float*)d_in[0];
    const float* w_qkv = (const float*)d_in[1];
    const float* w_out = (const float*)d_in[2];
    float* out = (float*)d_out;

    __half *xh, *w1h, *w2h, *qh, *ah;
    cudaGetSymbolAddress((void**)&xh, g_xh);
    cudaGetSymbolAddress((void**)&w1h, g_w1h);
    cudaGetSymbolAddress((void**)&w2h, g_w2h);
    cudaGetSymbolAddress((void**)&qh, g_qkvh);
    cudaGetSymbolAddress((void**)&ah, g_ah);

    cudaFuncSetAttribute(gemm_h<0>, cudaFuncAttributeMaxDynamicSharedMemorySize, GSMEM_BYTES);
    cudaFuncSetAttribute(gemm_h<1>, cudaFuncAttributeMaxDynamicSharedMemorySize, GSMEM_BYTES);
    cudaFuncSetAttribute(flash_mma, cudaFuncAttributeMaxDynamicSharedMemorySize, FSMEM);

    const int M = MDIM;

    cast_h<<<(M * DMODEL / 4 + 255) / 256, 256>>>(x, xh, M * DMODEL / 4);
    transpose_h<<<dim3(D3 / 32, DMODEL / 32), dim3(32, 8)>>>(w_qkv, w1h, DMODEL, D3);
    transpose_h<<<dim3(DMODEL / 32, DMODEL / 32), dim3(32, 8)>>>(w_out, w2h, DMODEL, DMODEL);

    // 1) qkv (fp16) = x @ w_qkv
    gemm_h<1><<<dim3(D3 / 128, M / 128), 256, GSMEM_BYTES>>>(
        xh, w1h, nullptr, qh, M, D3, DMODEL);

    // 2) tensor-core causal flash attention -> fp16 att
    flash_mma<<<dim3(SLEN / 128, HEADS, BATCH), 256, FSMEM>>>(qh, ah);

    // 3) out = att @ w_out (fp32 out)
    gemm_h<0><<<dim3(DMODEL / 128, M / 128), 256, GSMEM_BYTES>>>(
        ah, w2h, out, nullptr, M, DMODEL, DMODEL);
}

// round 12
// speedup vs baseline: 2.2838x; 1.0302x over previous
#include <cuda_runtime.h>
#include <cuda_fp16.h>
#include <cstdint>

// Problem constants
#define BATCH 2
#define SLEN 2048
#define DMODEL 1024
#define HEADS 16
#define HD 64
#define MDIM (BATCH * SLEN)   // 4096
#define D3 (3 * DMODEL)       // 3072

// ---------------------------------------------------------------------------
// Scratch (device globals; no allocations allowed)
// ---------------------------------------------------------------------------
__device__ __half g_xh[(size_t)MDIM * DMODEL];
__device__ __half g_w1h[(size_t)D3 * DMODEL];      // w_qkv^T [3D, D]
__device__ __half g_w2h[(size_t)DMODEL * DMODEL];  // w_out^T [D, D]
__device__ __half g_qkvh[(size_t)MDIM * D3];       // GEMM1 fp16 output
__device__ __half g_ah[(size_t)MDIM * DMODEL];     // attention fp16 output

// ---------------------------------------------------------------------------
// PTX helpers (sm_80+ only — harness targets base sm_100)
// ---------------------------------------------------------------------------
__device__ __forceinline__ uint32_t smem_u32(const void* p) {
    uint32_t a;
    asm("{ .reg .u64 t; cvta.to.shared.u64 t, %1; cvt.u32.u64 %0, t; }" : "=r"(a) : "l"(p));
    return a;
}
__device__ __forceinline__ void cp16(uint32_t dst, const void* src) {
    asm volatile("cp.async.cg.shared.global [%0], [%1], 16;" :: "r"(dst), "l"(src) : "memory");
}
#define CP_COMMIT() asm volatile("cp.async.commit_group;" ::: "memory")
#define CP_WAIT(n)  asm volatile("cp.async.wait_group %0;" :: "n"(n) : "memory")

#define LDM4(r, addr) \
    asm volatile("ldmatrix.sync.aligned.m8n8.x4.shared.b16 {%0,%1,%2,%3}, [%4];" \
        : "=r"((r)[0]), "=r"((r)[1]), "=r"((r)[2]), "=r"((r)[3]) : "r"(addr))
#define LDM4T(r, addr) \
    asm volatile("ldmatrix.sync.aligned.m8n8.x4.trans.shared.b16 {%0,%1,%2,%3}, [%4];" \
        : "=r"((r)[0]), "=r"((r)[1]), "=r"((r)[2]), "=r"((r)[3]) : "r"(addr))

#define MMA(d, a, b0, b1) \
    asm volatile("mma.sync.aligned.m16n8k16.row.col.f32.f16.f16.f32 " \
        "{%0,%1,%2,%3}, {%4,%5,%6,%7}, {%8,%9}, {%0,%1,%2,%3};" \
        : "+f"((d)[0]), "+f"((d)[1]), "+f"((d)[2]), "+f"((d)[3]) \
        : "r"((a)[0]), "r"((a)[1]), "r"((a)[2]), "r"((a)[3]), "r"(b0), "r"(b1))

__device__ __forceinline__ uint32_t packh(float a, float b) {
    __half2 t = __floats2half2_rn(a, b);
    return *reinterpret_cast<uint32_t*>(&t);
}

// Fast exp2: deg-4 poly + exponent stuffing. x <= 0 expected; ~1e-6 rel err.
__device__ __forceinline__ float exp2_fast(float x) {
    x = fmaxf(x, -126.0f);
    int xi = __float2int_rd(x);
    float f = x - (float)xi;
    float p = 0.0135557472f;
    p = fmaf(p, f, 0.0520323690f);
    p = fmaf(p, f, 0.2413797743f);
    p = fmaf(p, f, 0.6930321187f);
    p = fmaf(p, f, 1.0f);
    return __int_as_float((xi + 127) << 23) * p;
}

#define CEXP 0.1803368801111204f   // 0.125 * log2(e)

// ---------------------------------------------------------------------------
// Cast fp32 -> fp16 elementwise (vectorized by 4)
// ---------------------------------------------------------------------------
__global__ __launch_bounds__(256) void cast_h(
    const float* __restrict__ src, __half* __restrict__ dst, int n4)
{
    int i = blockIdx.x * blockDim.x + threadIdx.x;
    if (i >= n4) return;
    float4 v = reinterpret_cast<const float4*>(src)[i];
    uint2 hp;
    hp.x = packh(v.x, v.y);
    hp.y = packh(v.z, v.w);
    reinterpret_cast<uint2*>(dst)[i] = hp;
}

// ---------------------------------------------------------------------------
// Transpose to fp16: src [R, C] fp32 -> hT [C, R] fp16
// ---------------------------------------------------------------------------
__global__ __launch_bounds__(256) void transpose_h(
    const float* __restrict__ src, __half* __restrict__ hT, int R, int C)
{
    __shared__ float t[32][33];
    const int c0 = blockIdx.x * 32, r0 = blockIdx.y * 32;
    const int tx = threadIdx.x, ty = threadIdx.y;   // 32 x 8
    #pragma unroll
    for (int j = 0; j < 4; j++)
        t[ty + 8 * j][tx] = src[(size_t)(r0 + ty + 8 * j) * C + c0 + tx];
    __syncthreads();
    #pragma unroll
    for (int j = 0; j < 4; j++)
        hT[(size_t)(c0 + ty + 8 * j) * R + r0 + tx] = __float2half_rn(t[tx][ty + 8 * j]);
}

// ---------------------------------------------------------------------------
// Warp-MMA fp16 GEMM. C[M,N] = A[M,K] @ BT[N,K]^T, fp32 accumulate.
// CTA tile 128x128, 256 threads (8 warps, 2Mx4N), warp tile 64x32.
// 3-stage cp.async pipeline, ONE __syncthreads per chunk.
// 110.6 KB smem -> 2 CTAs/SM. HALF_OUT=1: fp16 out; else fp32.
// ---------------------------------------------------------------------------
#define A_MAT 18432            // 128 rows * 144 B
#define STAGE_BYTES 36864      // A + B
#define GSMEM_BYTES 110592     // 3 stages

template<int HALF_OUT>
__global__ __launch_bounds__(256, 2) void gemm_h(
    const __half* __restrict__ A, const __half* __restrict__ BT,
    float* __restrict__ C, __half* __restrict__ Ch,
    int M, int N, int K)
{
    extern __shared__ char smem[];
    const uint32_t sb = smem_u32(smem);
    const int tid = threadIdx.x;
    const int wid = tid >> 5, lane = tid & 31;
    const int m0 = blockIdx.y << 7, n0 = blockIdx.x << 7;
    const int wm = (wid >> 2) * 64, wn = (wid & 3) * 32;
    const int nc = K >> 6;

    const __half* gA = A + (size_t)m0 * K;
    const __half* gB = BT + (size_t)n0 * K;

    float acc[4][4][4];
    #pragma unroll
    for (int a = 0; a < 4; a++)
        #pragma unroll
        for (int b = 0; b < 4; b++)
            #pragma unroll
            for (int c = 0; c < 4; c++) acc[a][b][c] = 0.f;

    const int rA = lane & 15, hA = lane >> 4;
    const int qB = lane >> 3, r8 = lane & 7;
    const int bRow = (qB >> 1) * 8 + r8, bHalf = qB & 1;

    auto load_stage = [&](int st, int kk) {
        uint32_t base = sb + (uint32_t)st * STAGE_BYTES;
        #pragma unroll
        for (int j = 0; j < 4; j++) {     // A: 1024 chunks
            int idx = tid + j * 256;
            int row = idx >> 3, c = idx & 7;
            cp16(base + (uint32_t)(row * 144 + c * 16), gA + kk + (size_t)row * K + c * 8);
        }
        #pragma unroll
        for (int j = 0; j < 4; j++) {     // B: 1024 chunks
            int idx = tid + j * 256;
            int row = idx >> 3, c = idx & 7;
            cp16(base + A_MAT + (uint32_t)(row * 144 + c * 16), gB + kk + (size_t)row * K + c * 8);
        }
        CP_COMMIT();
    };

    auto compute_stage = [&](int st) {
        uint32_t base = sb + (uint32_t)st * STAGE_BYTES;
        const uint32_t sA = base, sB = base + A_MAT;
        #pragma unroll
        for (int ks = 0; ks < 4; ks++) {
            uint32_t aF[4][4], bF[2][4];
            #pragma unroll
            for (int mt = 0; mt < 4; mt++) {
                uint32_t off = (uint32_t)((wm + mt * 16 + rA) * 144 + ks * 32 + hA * 16);
                LDM4(aF[mt], sA + off);
            }
            #pragma unroll
            for (int bt = 0; bt < 2; bt++) {
                uint32_t off = (uint32_t)((wn + bt * 16 + bRow) * 144 + ks * 32 + bHalf * 16);
                LDM4(bF[bt], sB + off);
            }
            #pragma unroll
            for (int mt = 0; mt < 4; mt++)
                #pragma unroll
                for (int nt = 0; nt < 4; nt++) {
                    const int bt = nt >> 1, p = (nt & 1) * 2;
                    MMA(acc[mt][nt], aF[mt], bF[bt][p], bF[bt][p + 1]);
                }
        }
    };

    // 3-stage pipeline, one barrier per chunk.
    load_stage(0, 0);
    load_stage(1, 64);
    int sc = 0;                 // compute stage index (mod 3)
    for (int ic = 0; ic < nc; ic++) {
        if (ic + 1 < nc) { CP_WAIT(1); } else { CP_WAIT(0); }
        __syncthreads();        // visibility + all warps done with stage (ic-1)%3
        if (ic + 2 < nc) {
            int sld = sc + 2 >= 3 ? sc - 1 : sc + 2;
            load_stage(sld, (ic + 2) << 6);
        }
        compute_stage(sc);
        sc = (sc + 1 == 3) ? 0 : sc + 1;
    }

    const int rowb = lane >> 2, colb = (lane & 3) * 2;
    #pragma unroll
    for (int mt = 0; mt < 4; mt++)
        #pragma unroll
        for (int nt = 0; nt < 4; nt++) {
            const int r = m0 + wm + mt * 16 + rowb;
            const int cI = n0 + wn + nt * 8 + colb;
            float v0 = acc[mt][nt][0], v1 = acc[mt][nt][1];
            float v2 = acc[mt][nt][2], v3 = acc[mt][nt][3];
            if (HALF_OUT) {
                *(uint32_t*)&Ch[(size_t)r * N + cI]       = packh(v0, v1);
                *(uint32_t*)&Ch[(size_t)(r + 8) * N + cI] = packh(v2, v3);
            } else {
                *(float2*)&C[(size_t)r * N + cI]       = make_float2(v0, v1);
                *(float2*)&C[(size_t)(r + 8) * N + cI] = make_float2(v2, v3);
            }
        }
}

// ---------------------------------------------------------------------------
// Tensor-core causal flash attention, pure fp16 operands, fp32 accum/softmax.
// Q fragments hoisted to registers. CTA: 256 threads (8 warps), q-tile 128,
// k-tile 64, 3-stage cp.async KV pipeline, ONE __syncthreads per iteration.
// 73.7 KB smem -> 3 CTAs/SM.
// ---------------------------------------------------------------------------
#define FQ_BYTES 18432          // 128*144
#define FKV_MAT 9216            // 64*144
#define FSTAGE (2 * FKV_MAT)    // 18432 (K + V)
#define FSMEM (FQ_BYTES + 3 * FSTAGE)   // 73728

__global__ __launch_bounds__(256) void flash_mma(
    const __half* __restrict__ qkv, __half* __restrict__ outh)
{
    extern __shared__ char smem[];
    const uint32_t sb = smem_u32(smem);
    const uint32_t sQ = sb;
    const uint32_t sStage = sb + FQ_BYTES;

    const int tid = threadIdx.x, wid = tid >> 5, lane = tid & 31;
    const int q0 = ((int)gridDim.x - 1 - (int)blockIdx.x) * 128;
    const int h = blockIdx.y, b = blockIdx.z;
    const int qrow0 = q0 + wid * 16;

    const __half* baseP = qkv + (size_t)b * SLEN * D3 + h * HD;

    const int rA = lane & 15, hA = lane >> 4;              // A frag (Q rows)
    const int qB = lane >> 3, r8 = lane & 7;               // B frag (K rows)
    const int bRow = (qB >> 1) * 8 + r8, bHalf = qB & 1;
    const int grp = lane >> 3, l8 = lane & 7;              // V trans frag

    // Stage Q tile: 1024 chunks (committed as part of KV group 0)
    {
        #pragma unroll
        for (int j = 0; j < 4; j++) {
            int idx = tid + j * 256;
            int row = idx >> 3, c = idx & 7;
            cp16(sQ + (uint32_t)(row * 144 + c * 16),
                 baseP + (size_t)(q0 + row) * D3 + c * 8);
        }
    }

    const int nk = q0 / 64 + 2;   // always >= 2

    auto load_kv = [&](int st, int k0) {
        uint32_t base = sStage + (uint32_t)st * FSTAGE;
        #pragma unroll
        for (int j = 0; j < 4; j++) {   // K + V: 1024 chunks
            int idx = tid + j * 256;
            int mat = idx >> 9, row = (idx >> 3) & 63, c = idx & 7;
            int seg = mat ? 2 * DMODEL : DMODEL;   // 0=K, 1=V
            cp16(base + (uint32_t)mat * FKV_MAT + (uint32_t)(row * 144 + c * 16),
                 baseP + (size_t)(k0 + row) * D3 + seg + c * 8);
        }
        CP_COMMIT();
    };

    float oacc[8][4];
    #pragma unroll
    for (int i = 0; i < 8; i++)
        #pragma unroll
        for (int j = 0; j < 4; j++) oacc[i][j] = 0.f;
    float m0 = -1e30f, m1 = -1e30f, l0 = 0.f, l1 = 0.f;

    uint32_t qF[4][4];   // hoisted Q fragments (per ks)

    load_kv(0, 0);     // group0 = Q + KV0
    load_kv(1, 64);    // group1 = KV1

    int sc = 0;        // compute stage (mod 3)
    for (int it = 0; it < nk; it++) {
        const int k0 = it * 64;
        if (it + 1 < nk) { CP_WAIT(1); } else { CP_WAIT(0); }
        __syncthreads();   // stage sc ready for all; stage (it-1)%3 free for reuse

        if (it == 0) {     // Q resident now (group0); hoist frags once
            #pragma unroll
            for (int ks = 0; ks < 4; ks++) {
                uint32_t aoff = (uint32_t)((wid * 16 + rA) * 144 + ks * 32 + hA * 16);
                LDM4(qF[ks], sQ + aoff);
            }
        }

        if (it + 2 < nk) {
            int sld = sc + 2 >= 3 ? sc - 1 : sc + 2;
            load_kv(sld, (it + 2) * 64);
        }

        if (k0 <= qrow0 + 15) {
            const uint32_t st = sStage + (uint32_t)sc * FSTAGE;
            const uint32_t sK = st, sV = st + FKV_MAT;

            // ---- S = Q K^T, 16x64 per warp
            float sfrag[8][4];
            #pragma unroll
            for (int i = 0; i < 8; i++)
                #pragma unroll
                for (int j = 0; j < 4; j++) sfrag[i][j] = 0.f;

            #pragma unroll
            for (int ks = 0; ks < 4; ks++) {
                uint32_t kF[4][4];
                #pragma unroll
                for (int bt = 0; bt < 4; bt++) {
                    uint32_t off = (uint32_t)((bt * 16 + bRow) * 144 + ks * 32 + bHalf * 16);
                    LDM4(kF[bt], sK + off);
                }
                #pragma unroll
                for (int nt = 0; nt < 8; nt++) {
                    const int bt = nt >> 1, p = (nt & 1) * 2;
                    MMA(sfrag[nt], qF[ks], kF[bt][p], kF[bt][p + 1]);
                }
            }

            // ---- causal mask on diagonal tiles
            const int row0 = qrow0 + (lane >> 2), row1 = row0 + 8;
            if (k0 + 63 > qrow0) {
                #pragma unroll
                for (int nt = 0; nt < 8; nt++) {
                    int col = k0 + nt * 8 + ((lane & 3) << 1);
                    if (col > row0)     sfrag[nt][0] = -1e30f;
                    if (col + 1 > row0) sfrag[nt][1] = -1e30f;
                    if (col > row1)     sfrag[nt][2] = -1e30f;
                    if (col + 1 > row1) sfrag[nt][3] = -1e30f;
                }
            }

            // ---- online softmax
            float mc0 = -1e30f, mc1 = -1e30f;
            #pragma unroll
            for (int nt = 0; nt < 8; nt++) {
                mc0 = fmaxf(mc0, fmaxf(sfrag[nt][0], sfrag[nt][1]));
                mc1 = fmaxf(mc1, fmaxf(sfrag[nt][2], sfrag[nt][3]));
            }
            mc0 = fmaxf(mc0, __shfl_xor_sync(0xffffffffu, mc0, 1));
            mc0 = fmaxf(mc0, __shfl_xor_sync(0xffffffffu, mc0, 2));
            mc1 = fmaxf(mc1, __shfl_xor_sync(0xffffffffu, mc1, 1));
            mc1 = fmaxf(mc1, __shfl_xor_sync(0xffffffffu, mc1, 2));
            const float mn0 = fmaxf(m0, mc0), mn1 = fmaxf(m1, mc1);
            const float corr0 = exp2_fast((m0 - mn0) * CEXP);
            const float corr1 = exp2_fast((m1 - mn1) * CEXP);
            m0 = mn0; m1 = mn1;

            float rs0 = 0.f, rs1 = 0.f;
            #pragma unroll
            for (int nt = 0; nt < 8; nt++) {
                sfrag[nt][0] = exp2_fast((sfrag[nt][0] - mn0) * CEXP);
                sfrag[nt][1] = exp2_fast((sfrag[nt][1] - mn0) * CEXP);
                sfrag[nt][2] = exp2_fast((sfrag[nt][2] - mn1) * CEXP);
                sfrag[nt][3] = exp2_fast((sfrag[nt][3] - mn1) * CEXP);
                rs0 += sfrag[nt][0] + sfrag[nt][1];
                rs1 += sfrag[nt][2] + sfrag[nt][3];
            }
            rs0 += __shfl_xor_sync(0xffffffffu, rs0, 1);
            rs0 += __shfl_xor_sync(0xffffffffu, rs0, 2);
            rs1 += __shfl_xor_sync(0xffffffffu, rs1, 1);
            rs1 += __shfl_xor_sync(0xffffffffu, rs1, 2);
            l0 = l0 * corr0 + rs0;
            l1 = l1 * corr1 + rs1;
            #pragma unroll
            for (int nt = 0; nt < 8; nt++) {
                oacc[nt][0] *= corr0; oacc[nt][1] *= corr0;
                oacc[nt][2] *= corr1; oacc[nt][3] *= corr1;
            }

            // ---- O += P V (single fp16 P and V)
            #pragma unroll
            for (int t = 0; t < 4; t++) {
                uint32_t pF[4];
                pF[0] = packh(sfrag[2 * t][0], sfrag[2 * t][1]);
                pF[1] = packh(sfrag[2 * t][2], sfrag[2 * t][3]);
                pF[2] = packh(sfrag[2 * t + 1][0], sfrag[2 * t + 1][1]);
                pF[3] = packh(sfrag[2 * t + 1][2], sfrag[2 * t + 1][3]);
                #pragma unroll
                for (int np = 0; np < 4; np++) {
                    uint32_t vF[4];
                    uint32_t off = (uint32_t)((t * 16 + (grp & 1) * 8 + l8) * 144 +
                                              (np * 16 + (grp >> 1) * 8) * 2);
                    LDM4T(vF, sV + off);
                    MMA(oacc[np * 2],     pF, vF[0], vF[1]);
                    MMA(oacc[np * 2 + 1], pF, vF[2], vF[3]);
                }
            }
        }
        sc = (sc + 1 == 3) ? 0 : sc + 1;
    }

    // ---- finalize: O /= l, write fp16 output [B*S, D]
    const float inv0 = 1.f / l0, inv1 = 1.f / l1;
    const int row0 = q0 + wid * 16 + (lane >> 2);
    const int colb = h * HD + (lane & 3) * 2;
    #pragma unroll
    for (int nt = 0; nt < 8; nt++) {
        float v0 = oacc[nt][0] * inv0, v1 = oacc[nt][1] * inv0;
        float v2 = oacc[nt][2] * inv1, v3 = oacc[nt][3] * inv1;
        size_t o0 = (size_t)(b * SLEN + row0) * DMODEL + colb + nt * 8;
        size_t o1 = (size_t)(b * SLEN + row0 + 8) * DMODEL + colb + nt * 8;
        *(uint32_t*)&outh[o0] = packh(v0, v1);
        *(uint32_t*)&outh[o1] = packh(v2, v3);
    }
}

// ---------------------------------------------------------------------------
// kernel_launch
// ---------------------------------------------------------------------------
extern "C" void kernel_launch(void* const* d_in, const int* in_sizes, int n_in,
                              void* d_out, int out_size)
{
    const float* x     = (const float*)d_in[0];
    const float* w_qkv = (const float*)d_in[1];
    const float* w_out = (const float*)d_in[2];
    float* out = (float*)d_out;

    __half *xh, *w1h, *w2h, *qh, *ah;
    cudaGetSymbolAddress((void**)&xh, g_xh);
    cudaGetSymbolAddress((void**)&w1h, g_w1h);
    cudaGetSymbolAddress((void**)&w2h, g_w2h);
    cudaGetSymbolAddress((void**)&qh, g_qkvh);
    cudaGetSymbolAddress((void**)&ah, g_ah);

    cudaFuncSetAttribute(gemm_h<0>, cudaFuncAttributeMaxDynamicSharedMemorySize, GSMEM_BYTES);
    cudaFuncSetAttribute(gemm_h<1>, cudaFuncAttributeMaxDynamicSharedMemorySize, GSMEM_BYTES);
    cudaFuncSetAttribute(flash_mma, cudaFuncAttributeMaxDynamicSharedMemorySize, FSMEM);

    const int M = MDIM;

    cast_h<<<(M * DMODEL / 4 + 255) / 256, 256>>>(x, xh, M * DMODEL / 4);
    transpose_h<<<dim3(D3 / 32, DMODEL / 32), dim3(32, 8)>>>(w_qkv, w1h, DMODEL, D3);
    transpose_h<<<dim3(DMODEL / 32, DMODEL / 32), dim3(32, 8)>>>(w_out, w2h, DMODEL, DMODEL);

    // 1) qkv (fp16) = x @ w_qkv
    gemm_h<1><<<dim3(D3 / 128, M / 128), 256, GSMEM_BYTES>>>(
        xh, w1h, nullptr, qh, M, D3, DMODEL);

    // 2) tensor-core causal flash attention -> fp16 att
    flash_mma<<<dim3(SLEN / 128, HEADS, BATCH), 256, FSMEM>>>(qh, ah);

    // 3) out = att @ w_out (fp32 out)
    gemm_h<0><<<dim3(DMODEL / 128, M / 128), 256, GSMEM_BYTES>>>(
        ah, w2h, out, nullptr, M, DMODEL, DMODEL);
}